// round 1
// baseline (speedup 1.0000x reference)
#include <cuda_runtime.h>

#define BB 8
#define CC 64
#define HH 64
#define WW 64
#define OO 64
#define HWT (HH*WW)
#define JJ 27

// Scratch (device globals: no allocation allowed)
__device__ float g_nhwc[BB*HH*WW*CC];   // input_feat in NHWC
__device__ float g_om[BB*JJ*HWT];       // offset/mask conv output (B,27,H,W)
__device__ float g_wt[9*CC*OO];         // weight transposed to [k][c][o]

// ---------------------------------------------------------------------------
// Kernel 1: NCHW -> NHWC transpose of input_feat. One block per (b,h).
// ---------------------------------------------------------------------------
__global__ __launch_bounds__(256) void transpose_nhwc(const float* __restrict__ in) {
    int bh = blockIdx.x;
    int b = bh / HH, h = bh % HH;
    __shared__ float tile[CC][WW + 1];
    const float* src = in + ((size_t)b*CC)*HWT + (size_t)h*WW;
    for (int i = threadIdx.x; i < CC*WW; i += 256) {
        int c = i >> 6, w = i & 63;
        tile[c][w] = src[(size_t)c*HWT + w];
    }
    __syncthreads();
    float* dst = g_nhwc + (((size_t)b*HH + h)*WW)*CC;
    for (int i = threadIdx.x; i < CC*WW; i += 256) {
        int w = i >> 6, c = i & 63;
        dst[w*CC + c] = tile[c][w];
    }
}

// ---------------------------------------------------------------------------
// Kernel 2: weight (O,C,3,3) -> g_wt[k][c][o]
// ---------------------------------------------------------------------------
__global__ void transpose_w(const float* __restrict__ w) {
    int i = blockIdx.x * blockDim.x + threadIdx.x;
    if (i < 9*CC*OO) {
        int k = i / (CC*OO);
        int r = i % (CC*OO);
        int c = r >> 6;
        int o = r & 63;
        g_wt[i] = w[(o*CC + c)*9 + k];
    }
}

// ---------------------------------------------------------------------------
// Kernel 3: om = conv3x3(concat(input_feat, degrad), om_weight) + om_bias
// One block per (b, 16x16 tile). acc[27] per thread (thread = pixel).
// ---------------------------------------------------------------------------
__global__ __launch_bounds__(256) void om_conv(const float* __restrict__ feat,
                                               const float* __restrict__ deg,
                                               const float* __restrict__ omw,
                                               const float* __restrict__ omb) {
    int b  = blockIdx.y;
    int tY = blockIdx.x >> 2;   // 4 tiles per dim (64/16)
    int tX = blockIdx.x & 3;
    __shared__ float s_in[16 * 18 * 18];  // 16 channels, 18x18 halo tile
    __shared__ float s_w[16 * 9 * JJ];    // [ci][tap][j]
    int t  = threadIdx.x;
    int tx = t & 15, ty = t >> 4;
    int y0 = tY * 16, x0 = tX * 16;

    float acc[JJ];
#pragma unroll
    for (int j = 0; j < JJ; j++) acc[j] = 0.f;

    for (int cc = 0; cc < 8; cc++) {
        int ci0 = cc * 16;
        // Load input halo tile (zeros outside)
        for (int i = t; i < 16 * 324; i += 256) {
            int ci = i / 324;
            int r  = i % 324;
            int yy = r / 18 + y0 - 1;
            int xx = r % 18 + x0 - 1;
            float v = 0.f;
            if (yy >= 0 && yy < HH && xx >= 0 && xx < WW) {
                int gci = ci0 + ci;
                const float* src = (gci < CC) ? feat : deg;
                v = src[(((size_t)b*CC + (gci & 63))*HH + yy)*WW + xx];
            }
            s_in[i] = v;
        }
        // Load weight chunk, enumerating source-contiguously for coalescing
        for (int i = t; i < JJ * 16 * 9; i += 256) {
            int j   = i / 144;
            int r   = i % 144;
            int ci  = r / 9;
            int tap = r % 9;
            s_w[(ci * 9 + tap) * JJ + j] = omw[(j * 128 + ci0 + ci) * 9 + tap];
        }
        __syncthreads();

        for (int ci = 0; ci < 16; ci++) {
            const float* bi = &s_in[ci * 324 + ty * 18 + tx];
            const float* bw = &s_w[ci * 9 * JJ];
#pragma unroll
            for (int tap = 0; tap < 9; tap++) {
                float v = bi[(tap / 3) * 18 + (tap % 3)];
                const float* wp = &bw[tap * JJ];
#pragma unroll
                for (int j = 0; j < JJ; j++) acc[j] = fmaf(v, wp[j], acc[j]);
            }
        }
        __syncthreads();
    }

    int gy = y0 + ty, gx = x0 + tx;
    int p  = gy * WW + gx;
#pragma unroll
    for (int j = 0; j < JJ; j++)
        g_om[((size_t)b * JJ + j) * HWT + p] = acc[j] + omb[j];
}

// ---------------------------------------------------------------------------
// Kernel 4: deformable conv. One block per (b, 8x8 pixel tile).
// Per k: coords+mask -> smem, bilinear sample 64c x 64px (NHWC float4 gathers)
// -> smem, then 64x64 @ 64x64 micro-GEMM (4x4 per thread), accumulate over k.
// ---------------------------------------------------------------------------
__device__ __forceinline__ void acc_corner(float4* a, const float* ptr, float w) {
    const float4* p = (const float4*)ptr;
#pragma unroll
    for (int q = 0; q < 4; q++) {
        float4 v = p[q];
        a[q].x = fmaf(w, v.x, a[q].x);
        a[q].y = fmaf(w, v.y, a[q].y);
        a[q].z = fmaf(w, v.z, a[q].z);
        a[q].w = fmaf(w, v.w, a[q].w);
    }
}

__global__ __launch_bounds__(256) void deform(float* __restrict__ out) {
    int bi   = blockIdx.x;
    int b    = bi >> 6;
    int tile = bi & 63;
    int tY   = tile >> 3, tX = tile & 7;

    __shared__ float s_samp[CC * 64];   // [c][px]
    __shared__ float s_w[CC * OO];      // [c][o]
    __shared__ float s_y[64], s_x[64], s_m[64];

    int t = threadIdx.x;
    float acc[4][4];
#pragma unroll
    for (int i = 0; i < 4; i++)
#pragma unroll
        for (int j = 0; j < 4; j++) acc[i][j] = 0.f;

    const float* omb_ = g_om + (size_t)b * JJ * HWT;

    for (int k = 0; k < 9; k++) {
        // coordinates + mask for this k (first 64 threads)
        if (t < 64) {
            int ly = t >> 3, lx = t & 7;
            int gy = tY * 8 + ly, gx = tX * 8 + lx;
            int p  = gy * WW + gx;
            float dy = omb_[(2 * k) * HWT + p];
            float dx = omb_[(2 * k + 1) * HWT + p];
            float mv = omb_[(18 + k) * HWT + p];
            s_m[t] = 1.f / (1.f + __expf(-mv));
            s_y[t] = (float)(gy - 1 + k / 3) + dy;
            s_x[t] = (float)(gx - 1 + k % 3) + dx;
        }
        // weight slice [c][o] for this k (all threads, coalesced)
#pragma unroll
        for (int j = 0; j < 16; j++)
            s_w[j * 256 + t] = g_wt[k * 4096 + j * 256 + t];
        __syncthreads();

        // Bilinear sampling: thread = (px, 16-channel group)
        {
            int px = t & 63, cg = t >> 6;
            float y = s_y[px], x = s_x[px], m = s_m[px];
            float yf = floorf(y), xf = floorf(x);
            int iy0 = (int)yf, ix0 = (int)xf;
            float wy = y - yf, wx = x - xf;
            float w00 = (1.f - wy) * (1.f - wx) * m;
            float w01 = (1.f - wy) * wx * m;
            float w10 = wy * (1.f - wx) * m;
            float w11 = wy * wx * m;
            bool vy0 = (iy0 >= 0 && iy0 < HH);
            bool vy1 = (iy0 >= -1 && iy0 < HH - 1);
            bool vx0 = (ix0 >= 0 && ix0 < WW);
            bool vx1 = (ix0 >= -1 && ix0 < WW - 1);

            const float* basep = g_nhwc + (size_t)b * HH * WW * CC + cg * 16;
            float4 a[4];
#pragma unroll
            for (int q = 0; q < 4; q++) a[q] = make_float4(0.f, 0.f, 0.f, 0.f);

            if (vy0 && vx0) acc_corner(a, basep + (iy0 * WW + ix0) * CC, w00);
            if (vy0 && vx1) acc_corner(a, basep + (iy0 * WW + ix0 + 1) * CC, w01);
            if (vy1 && vx0) acc_corner(a, basep + ((iy0 + 1) * WW + ix0) * CC, w10);
            if (vy1 && vx1) acc_corner(a, basep + ((iy0 + 1) * WW + ix0 + 1) * CC, w11);

            int c0 = cg * 16;
#pragma unroll
            for (int q = 0; q < 4; q++) {
                s_samp[(c0 + q * 4 + 0) * 64 + px] = a[q].x;
                s_samp[(c0 + q * 4 + 1) * 64 + px] = a[q].y;
                s_samp[(c0 + q * 4 + 2) * 64 + px] = a[q].z;
                s_samp[(c0 + q * 4 + 3) * 64 + px] = a[q].w;
            }
        }
        __syncthreads();

        // Micro-GEMM: out[o][px] += sum_c w[c][o] * samp[c][px]
        {
            int o4 = t >> 4, p4 = t & 15;
            const float4* wr = (const float4*)s_w;
            const float4* sr = (const float4*)s_samp;
#pragma unroll 8
            for (int c = 0; c < CC; c++) {
                float4 wv = wr[c * 16 + o4];
                float4 sv = sr[c * 16 + p4];
                acc[0][0] = fmaf(wv.x, sv.x, acc[0][0]);
                acc[0][1] = fmaf(wv.x, sv.y, acc[0][1]);
                acc[0][2] = fmaf(wv.x, sv.z, acc[0][2]);
                acc[0][3] = fmaf(wv.x, sv.w, acc[0][3]);
                acc[1][0] = fmaf(wv.y, sv.x, acc[1][0]);
                acc[1][1] = fmaf(wv.y, sv.y, acc[1][1]);
                acc[1][2] = fmaf(wv.y, sv.z, acc[1][2]);
                acc[1][3] = fmaf(wv.y, sv.w, acc[1][3]);
                acc[2][0] = fmaf(wv.z, sv.x, acc[2][0]);
                acc[2][1] = fmaf(wv.z, sv.y, acc[2][1]);
                acc[2][2] = fmaf(wv.z, sv.z, acc[2][2]);
                acc[2][3] = fmaf(wv.z, sv.w, acc[2][3]);
                acc[3][0] = fmaf(wv.w, sv.x, acc[3][0]);
                acc[3][1] = fmaf(wv.w, sv.y, acc[3][1]);
                acc[3][2] = fmaf(wv.w, sv.z, acc[3][2]);
                acc[3][3] = fmaf(wv.w, sv.w, acc[3][3]);
            }
        }
        __syncthreads();
    }

    // Writeback (B,O,H,W)
    int o4 = t >> 4, p4 = t & 15;
#pragma unroll
    for (int oi = 0; oi < 4; oi++) {
        int o = o4 * 4 + oi;
#pragma unroll
        for (int pi = 0; pi < 4; pi++) {
            int px = p4 * 4 + pi;
            int gy = tY * 8 + (px >> 3);
            int gx = tX * 8 + (px & 7);
            out[(((size_t)b * OO + o) * HH + gy) * WW + gx] = acc[oi][pi];
        }
    }
}

// ---------------------------------------------------------------------------
extern "C" void kernel_launch(void* const* d_in, const int* in_sizes, int n_in,
                              void* d_out, int out_size) {
    const float* input_feat = (const float*)d_in[0];
    const float* degrad     = (const float*)d_in[1];
    const float* weight     = (const float*)d_in[2];
    const float* om_weight  = (const float*)d_in[3];
    const float* om_bias    = (const float*)d_in[4];
    float* out = (float*)d_out;

    transpose_nhwc<<<BB * HH, 256>>>(input_feat);
    transpose_w<<<(9 * CC * OO + 255) / 256, 256>>>(weight);
    om_conv<<<dim3(16, BB), 256>>>(input_feat, degrad, om_weight, om_bias);
    deform<<<BB * 64, 256>>>(out);
}

// round 2
// speedup vs baseline: 1.3326x; 1.3326x over previous
#include <cuda_runtime.h>

#define BB 8
#define CC 64
#define HH 64
#define WW 64
#define OO 64
#define HWT (HH*WW)
#define JJ 27
#define JP 28   // padded j for float4 weight rows

// Scratch (device globals: no allocation allowed)
__device__ float g_nhwc[BB*HH*WW*CC];        // input_feat in NHWC
__device__ float g_om[BB*JJ*HWT];            // offset/mask conv output (B,27,H,W)
__device__ float g_wt[9*CC*OO];              // weight transposed to [k][c][o]
__device__ float g_part[8*BB*JJ*HWT];        // om partial sums per channel-chunk

// ---------------------------------------------------------------------------
// Kernel 1: NCHW -> NHWC transpose of input_feat. One block per (b,h).
// ---------------------------------------------------------------------------
__global__ __launch_bounds__(256) void transpose_nhwc(const float* __restrict__ in) {
    int bh = blockIdx.x;
    int b = bh / HH, h = bh % HH;
    __shared__ float tile[CC][WW + 1];
    const float* src = in + ((size_t)b*CC)*HWT + (size_t)h*WW;
    for (int i = threadIdx.x; i < CC*WW; i += 256) {
        int c = i >> 6, w = i & 63;
        tile[c][w] = src[(size_t)c*HWT + w];
    }
    __syncthreads();
    float* dst = g_nhwc + (((size_t)b*HH + h)*WW)*CC;
    for (int i = threadIdx.x; i < CC*WW; i += 256) {
        int w = i >> 6, c = i & 63;
        dst[w*CC + c] = tile[c][w];
    }
}

// ---------------------------------------------------------------------------
// Kernel 2: weight (O,C,3,3) -> g_wt[k][c][o]
// ---------------------------------------------------------------------------
__global__ void transpose_w(const float* __restrict__ w) {
    int i = blockIdx.x * blockDim.x + threadIdx.x;
    if (i < 9*CC*OO) {
        int k = i / (CC*OO);
        int r = i % (CC*OO);
        int c = r >> 6;
        int o = r & 63;
        g_wt[i] = w[(o*CC + c)*9 + k];
    }
}

// ---------------------------------------------------------------------------
// Kernel 3: om partial conv. Block = (spatial 8 rows x 64 cols, 16-ch chunk).
// 128 threads, 4 px per thread, acc = float4 acc[28] (28th j padded to zero).
// grid = (64 spatial-blocks, 8 chunks).
// ---------------------------------------------------------------------------
__global__ __launch_bounds__(128, 3) void om_conv(const float* __restrict__ feat,
                                                  const float* __restrict__ deg,
                                                  const float* __restrict__ omw) {
    int chunk = blockIdx.y;                 // 0..7 (16 input channels each)
    int sb = blockIdx.x;                    // 0..63
    int b = sb >> 3;
    int row0 = (sb & 7) * 8;

    __shared__ float s_in[16 * 10 * 66];    // 16 ch, rows [row0-1, row0+8], cols [-1,64]
    __shared__ float s_w[16 * 9 * JP];      // [ci][tap][jpad]

    int t = threadIdx.x;

    // weight chunk (pad j=27 with zero)
    for (int i = t; i < 16 * 9 * JP; i += 128) {
        int j = i % JP;
        int tap = (i / JP) % 9;
        int ci = i / (9 * JP);
        s_w[i] = (j < JJ) ? omw[(j * 128 + chunk * 16 + ci) * 9 + tap] : 0.f;
    }
    // input halo tile
    for (int i = t; i < 16 * 660; i += 128) {
        int ci = i / 660;
        int r = i % 660;
        int yy = r / 66 + row0 - 1;
        int xx = r % 66 - 1;
        float v = 0.f;
        if (yy >= 0 && yy < HH && xx >= 0 && xx < WW) {
            int gc = chunk * 16 + ci;
            const float* src = (gc < CC) ? feat : deg;
            v = src[(((size_t)b * CC + (gc & 63)) * HH + yy) * WW + xx];
        }
        s_in[i] = v;
    }
    __syncthreads();

    int trow = t >> 4;            // 0..7
    int tc4 = (t & 15) * 4;       // 0..60 (4 consecutive output cols)

    float4 acc[JP];
#pragma unroll
    for (int j = 0; j < JP; j++) acc[j] = make_float4(0.f, 0.f, 0.f, 0.f);

    for (int ci = 0; ci < 16; ci++) {
        const float* bi = s_in + ci * 660 + trow * 66 + tc4;
        const float* bw = s_w + ci * 9 * JP;
#pragma unroll
        for (int ky = 0; ky < 3; ky++) {
            float v0 = bi[ky*66 + 0], v1 = bi[ky*66 + 1], v2 = bi[ky*66 + 2];
            float v3 = bi[ky*66 + 3], v4 = bi[ky*66 + 4], v5 = bi[ky*66 + 5];
#pragma unroll
            for (int kx = 0; kx < 3; kx++) {
                float a = (kx == 0) ? v0 : (kx == 1) ? v1 : v2;
                float bb2 = (kx == 0) ? v1 : (kx == 1) ? v2 : v3;
                float cc2 = (kx == 0) ? v2 : (kx == 1) ? v3 : v4;
                float dd = (kx == 0) ? v3 : (kx == 1) ? v4 : v5;
                const float4* wr = (const float4*)(bw + (ky * 3 + kx) * JP);
#pragma unroll
                for (int jv = 0; jv < 7; jv++) {
                    float4 wv = wr[jv];
                    float4* a0 = &acc[jv*4 + 0];
                    a0->x = fmaf(wv.x, a, a0->x);  a0->y = fmaf(wv.x, bb2, a0->y);
                    a0->z = fmaf(wv.x, cc2, a0->z); a0->w = fmaf(wv.x, dd, a0->w);
                    float4* a1 = &acc[jv*4 + 1];
                    a1->x = fmaf(wv.y, a, a1->x);  a1->y = fmaf(wv.y, bb2, a1->y);
                    a1->z = fmaf(wv.y, cc2, a1->z); a1->w = fmaf(wv.y, dd, a1->w);
                    float4* a2 = &acc[jv*4 + 2];
                    a2->x = fmaf(wv.z, a, a2->x);  a2->y = fmaf(wv.z, bb2, a2->y);
                    a2->z = fmaf(wv.z, cc2, a2->z); a2->w = fmaf(wv.z, dd, a2->w);
                    float4* a3 = &acc[jv*4 + 3];
                    a3->x = fmaf(wv.w, a, a3->x);  a3->y = fmaf(wv.w, bb2, a3->y);
                    a3->z = fmaf(wv.w, cc2, a3->z); a3->w = fmaf(wv.w, dd, a3->w);
                }
            }
        }
    }

    // Partial store: g_part[chunk][b][j][p], p contiguous float4
    float* dst = g_part + (((size_t)chunk * BB + b) * JJ) * HWT + (row0 + trow) * WW + tc4;
#pragma unroll
    for (int j = 0; j < JJ; j++)
        *(float4*)(dst + (size_t)j * HWT) = acc[j];
}

// ---------------------------------------------------------------------------
// Kernel 3b: reduce partials over 8 chunks + bias -> g_om
// ---------------------------------------------------------------------------
__global__ __launch_bounds__(256) void reduce_om(const float* __restrict__ omb) {
    int i = blockIdx.x * 256 + threadIdx.x;     // over BB*JJ*1024 float4s
    if (i >= BB * JJ * (HWT / 4)) return;
    int p4 = i & 1023;
    int j = (i >> 10) % JJ;
    int b = i / (JJ * 1024);
    float bias = omb[j];
    float4 s = make_float4(bias, bias, bias, bias);
#pragma unroll
    for (int ch = 0; ch < 8; ch++) {
        float4 v = ((const float4*)g_part)[(((size_t)ch * BB + b) * JJ + j) * 1024 + p4];
        s.x += v.x; s.y += v.y; s.z += v.z; s.w += v.w;
    }
    ((float4*)g_om)[(((size_t)b) * JJ + j) * 1024 + p4] = s;
}

// ---------------------------------------------------------------------------
// Kernel 4: deformable conv. Block = (b, 8x16 px tile) -> 64o x 128px.
// Per k: coords+mask+weights -> smem, bilinear sample 64c x 128px, then
// micro-GEMM 8o x 4px per thread (FMA-bound: 48B LDS / 32 FMA).
// ---------------------------------------------------------------------------
__device__ __forceinline__ void acc_corner8(float4* a, const float* ptr, float w) {
    const float4* p = (const float4*)ptr;
#pragma unroll
    for (int q = 0; q < 8; q++) {
        float4 v = p[q];
        a[q].x = fmaf(w, v.x, a[q].x);
        a[q].y = fmaf(w, v.y, a[q].y);
        a[q].z = fmaf(w, v.z, a[q].z);
        a[q].w = fmaf(w, v.w, a[q].w);
    }
}

__global__ __launch_bounds__(256, 2) void deform(float* __restrict__ out) {
    int bi = blockIdx.x;            // 256 blocks: b(8) x tY(8) x tX(4)
    int b  = bi >> 5;
    int tY = (bi >> 2) & 7;
    int tX = bi & 3;

    __shared__ float s_samp[CC * 128];   // [c][px]
    __shared__ float s_w[CC * OO];       // [c][o]
    __shared__ float s_y[128], s_x[128], s_m[128];

    int t = threadIdx.x;
    float4 acc8[8];                      // 8 o x 4 px
#pragma unroll
    for (int i = 0; i < 8; i++) acc8[i] = make_float4(0.f, 0.f, 0.f, 0.f);

    const float* omb_ = g_om + (size_t)b * JJ * HWT;
    const float* img  = g_nhwc + (size_t)b * HH * WW * CC;

    for (int k = 0; k < 9; k++) {
        // coords + mask for the 128 pixels
        if (t < 128) {
            int ly = t >> 4, lx = t & 15;
            int gy = tY * 8 + ly, gx = tX * 16 + lx;
            int p = gy * WW + gx;
            float dy = omb_[(2 * k) * HWT + p];
            float dx = omb_[(2 * k + 1) * HWT + p];
            float mv = omb_[(18 + k) * HWT + p];
            s_m[t] = 1.f / (1.f + __expf(-mv));
            s_y[t] = (float)(gy - 1 + k / 3) + dy;
            s_x[t] = (float)(gx - 1 + k % 3) + dx;
        }
        // weight slice [c][o]
        {
            const float4* src = (const float4*)(g_wt + k * 4096);
            float4* dst = (float4*)s_w;
#pragma unroll
            for (int q = 0; q < 4; q++) dst[q * 256 + t] = src[q * 256 + t];
        }
        __syncthreads();

        // Bilinear sampling: thread = (px 0..127, 32-channel half)
        {
            int px = t & 127, c0 = (t >> 7) * 32;
            float y = s_y[px], x = s_x[px], m = s_m[px];
            float yf = floorf(y), xf = floorf(x);
            int iy0 = (int)yf, ix0 = (int)xf;
            float wy = y - yf, wx = x - xf;
            float w00 = (1.f - wy) * (1.f - wx) * m;
            float w01 = (1.f - wy) * wx * m;
            float w10 = wy * (1.f - wx) * m;
            float w11 = wy * wx * m;
            bool vy0 = (iy0 >= 0 && iy0 < HH);
            bool vy1 = (iy0 >= -1 && iy0 < HH - 1);
            bool vx0 = (ix0 >= 0 && ix0 < WW);
            bool vx1 = (ix0 >= -1 && ix0 < WW - 1);

            const float* basep = img + c0;
            float4 a[8];
#pragma unroll
            for (int q = 0; q < 8; q++) a[q] = make_float4(0.f, 0.f, 0.f, 0.f);

            if (vy0 && vx0) acc_corner8(a, basep + (iy0 * WW + ix0) * CC, w00);
            if (vy0 && vx1) acc_corner8(a, basep + (iy0 * WW + ix0 + 1) * CC, w01);
            if (vy1 && vx0) acc_corner8(a, basep + ((iy0 + 1) * WW + ix0) * CC, w10);
            if (vy1 && vx1) acc_corner8(a, basep + ((iy0 + 1) * WW + ix0 + 1) * CC, w11);

#pragma unroll
            for (int q = 0; q < 8; q++) {
                int c = c0 + q * 4;
                s_samp[(c + 0) * 128 + px] = a[q].x;
                s_samp[(c + 1) * 128 + px] = a[q].y;
                s_samp[(c + 2) * 128 + px] = a[q].z;
                s_samp[(c + 3) * 128 + px] = a[q].w;
            }
        }
        __syncthreads();

        // Micro-GEMM: 8 o (via two broadcast float4 weight loads) x 4 px
        {
            int o8 = t >> 5;                 // 0..7 -> o = o8*8..+7
            int sidx = t & 31;               // float4 px index
            const float4* wr = (const float4*)s_w;
            const float4* sr = (const float4*)s_samp;
#pragma unroll 8
            for (int c = 0; c < CC; c++) {
                float4 w0 = wr[c * 16 + o8 * 2];
                float4 w1 = wr[c * 16 + o8 * 2 + 1];
                float4 sv = sr[c * 32 + sidx];
                acc8[0].x = fmaf(w0.x, sv.x, acc8[0].x); acc8[0].y = fmaf(w0.x, sv.y, acc8[0].y);
                acc8[0].z = fmaf(w0.x, sv.z, acc8[0].z); acc8[0].w = fmaf(w0.x, sv.w, acc8[0].w);
                acc8[1].x = fmaf(w0.y, sv.x, acc8[1].x); acc8[1].y = fmaf(w0.y, sv.y, acc8[1].y);
                acc8[1].z = fmaf(w0.y, sv.z, acc8[1].z); acc8[1].w = fmaf(w0.y, sv.w, acc8[1].w);
                acc8[2].x = fmaf(w0.z, sv.x, acc8[2].x); acc8[2].y = fmaf(w0.z, sv.y, acc8[2].y);
                acc8[2].z = fmaf(w0.z, sv.z, acc8[2].z); acc8[2].w = fmaf(w0.z, sv.w, acc8[2].w);
                acc8[3].x = fmaf(w0.w, sv.x, acc8[3].x); acc8[3].y = fmaf(w0.w, sv.y, acc8[3].y);
                acc8[3].z = fmaf(w0.w, sv.z, acc8[3].z); acc8[3].w = fmaf(w0.w, sv.w, acc8[3].w);
                acc8[4].x = fmaf(w1.x, sv.x, acc8[4].x); acc8[4].y = fmaf(w1.x, sv.y, acc8[4].y);
                acc8[4].z = fmaf(w1.x, sv.z, acc8[4].z); acc8[4].w = fmaf(w1.x, sv.w, acc8[4].w);
                acc8[5].x = fmaf(w1.y, sv.x, acc8[5].x); acc8[5].y = fmaf(w1.y, sv.y, acc8[5].y);
                acc8[5].z = fmaf(w1.y, sv.z, acc8[5].z); acc8[5].w = fmaf(w1.y, sv.w, acc8[5].w);
                acc8[6].x = fmaf(w1.z, sv.x, acc8[6].x); acc8[6].y = fmaf(w1.z, sv.y, acc8[6].y);
                acc8[6].z = fmaf(w1.z, sv.z, acc8[6].z); acc8[6].w = fmaf(w1.z, sv.w, acc8[6].w);
                acc8[7].x = fmaf(w1.w, sv.x, acc8[7].x); acc8[7].y = fmaf(w1.w, sv.y, acc8[7].y);
                acc8[7].z = fmaf(w1.w, sv.z, acc8[7].z); acc8[7].w = fmaf(w1.w, sv.w, acc8[7].w);
            }
        }
        __syncthreads();
    }

    // Writeback (B,O,H,W): px4 = 4 consecutive cols in one row -> float4 store
    int o8 = t >> 5;
    int px4 = (t & 31) * 4;
    int gy = tY * 8 + (px4 >> 4);
    int gx = tX * 16 + (px4 & 15);
#pragma unroll
    for (int oi = 0; oi < 8; oi++) {
        int o = o8 * 8 + oi;
        *(float4*)(out + (((size_t)b * OO + o) * HH + gy) * WW + gx) = acc8[oi];
    }
}

// ---------------------------------------------------------------------------
extern "C" void kernel_launch(void* const* d_in, const int* in_sizes, int n_in,
                              void* d_out, int out_size) {
    const float* input_feat = (const float*)d_in[0];
    const float* degrad     = (const float*)d_in[1];
    const float* weight     = (const float*)d_in[2];
    const float* om_weight  = (const float*)d_in[3];
    const float* om_bias    = (const float*)d_in[4];
    float* out = (float*)d_out;

    transpose_nhwc<<<BB * HH, 256>>>(input_feat);
    transpose_w<<<(9 * CC * OO + 255) / 256, 256>>>(weight);
    om_conv<<<dim3(64, 8), 128>>>(input_feat, degrad, om_weight);
    reduce_om<<<(BB * JJ * (HWT / 4) + 255) / 256, 256>>>(om_bias);
    deform<<<BB * 32, 256>>>(out);
}

// round 3
// speedup vs baseline: 1.6172x; 1.2136x over previous
#include <cuda_runtime.h>

#define BB 8
#define CC 64
#define HH 64
#define WW 64
#define OO 64
#define HWT (HH*WW)
#define JJ 27
#define JP 28   // padded j for float4 weight rows

// Scratch (device globals: no allocation allowed)
__device__ float g_nhwc[BB*HH*WW*CC];        // input_feat in NHWC
__device__ float g_om[BB*JJ*HWT];            // offset/mask conv output (B,27,H,W)
__device__ float g_wt[9*CC*OO];              // weight transposed to [k][c][o]
__device__ float g_part[8*BB*JJ*HWT];        // om partial sums per channel-chunk

// ---------------------------------------------------------------------------
// Kernel 1: NCHW -> NHWC transpose of input_feat. One block per (b,h).
// ---------------------------------------------------------------------------
__global__ __launch_bounds__(256) void transpose_nhwc(const float* __restrict__ in) {
    int bh = blockIdx.x;
    int b = bh / HH, h = bh % HH;
    __shared__ float tile[CC][WW + 1];
    const float* src = in + ((size_t)b*CC)*HWT + (size_t)h*WW;
    for (int i = threadIdx.x; i < CC*WW; i += 256) {
        int c = i >> 6, w = i & 63;
        tile[c][w] = src[(size_t)c*HWT + w];
    }
    __syncthreads();
    float* dst = g_nhwc + (((size_t)b*HH + h)*WW)*CC;
    for (int i = threadIdx.x; i < CC*WW; i += 256) {
        int w = i >> 6, c = i & 63;
        dst[w*CC + c] = tile[c][w];
    }
}

// ---------------------------------------------------------------------------
// Kernel 2: weight (O,C,3,3) -> g_wt[k][c][o]
// ---------------------------------------------------------------------------
__global__ void transpose_w(const float* __restrict__ w) {
    int i = blockIdx.x * blockDim.x + threadIdx.x;
    if (i < 9*CC*OO) {
        int k = i / (CC*OO);
        int r = i % (CC*OO);
        int c = r >> 6;
        int o = r & 63;
        g_wt[i] = w[(o*CC + c)*9 + k];
    }
}

// ---------------------------------------------------------------------------
// Kernel 3: om partial conv (unchanged from R2: FMA-issue bound).
// ---------------------------------------------------------------------------
__global__ __launch_bounds__(128, 3) void om_conv(const float* __restrict__ feat,
                                                  const float* __restrict__ deg,
                                                  const float* __restrict__ omw) {
    int chunk = blockIdx.y;
    int sb = blockIdx.x;
    int b = sb >> 3;
    int row0 = (sb & 7) * 8;

    __shared__ float s_in[16 * 10 * 66];
    __shared__ float s_w[16 * 9 * JP];

    int t = threadIdx.x;

    for (int i = t; i < 16 * 9 * JP; i += 128) {
        int j = i % JP;
        int tap = (i / JP) % 9;
        int ci = i / (9 * JP);
        s_w[i] = (j < JJ) ? omw[(j * 128 + chunk * 16 + ci) * 9 + tap] : 0.f;
    }
    for (int i = t; i < 16 * 660; i += 128) {
        int ci = i / 660;
        int r = i % 660;
        int yy = r / 66 + row0 - 1;
        int xx = r % 66 - 1;
        float v = 0.f;
        if (yy >= 0 && yy < HH && xx >= 0 && xx < WW) {
            int gc = chunk * 16 + ci;
            const float* src = (gc < CC) ? feat : deg;
            v = src[(((size_t)b * CC + (gc & 63)) * HH + yy) * WW + xx];
        }
        s_in[i] = v;
    }
    __syncthreads();

    int trow = t >> 4;
    int tc4 = (t & 15) * 4;

    float4 acc[JP];
#pragma unroll
    for (int j = 0; j < JP; j++) acc[j] = make_float4(0.f, 0.f, 0.f, 0.f);

    for (int ci = 0; ci < 16; ci++) {
        const float* bi = s_in + ci * 660 + trow * 66 + tc4;
        const float* bw = s_w + ci * 9 * JP;
#pragma unroll
        for (int ky = 0; ky < 3; ky++) {
            float v0 = bi[ky*66 + 0], v1 = bi[ky*66 + 1], v2 = bi[ky*66 + 2];
            float v3 = bi[ky*66 + 3], v4 = bi[ky*66 + 4], v5 = bi[ky*66 + 5];
#pragma unroll
            for (int kx = 0; kx < 3; kx++) {
                float a = (kx == 0) ? v0 : (kx == 1) ? v1 : v2;
                float bb2 = (kx == 0) ? v1 : (kx == 1) ? v2 : v3;
                float cc2 = (kx == 0) ? v2 : (kx == 1) ? v3 : v4;
                float dd = (kx == 0) ? v3 : (kx == 1) ? v4 : v5;
                const float4* wr = (const float4*)(bw + (ky * 3 + kx) * JP);
#pragma unroll
                for (int jv = 0; jv < 7; jv++) {
                    float4 wv = wr[jv];
                    float4* a0 = &acc[jv*4 + 0];
                    a0->x = fmaf(wv.x, a, a0->x);  a0->y = fmaf(wv.x, bb2, a0->y);
                    a0->z = fmaf(wv.x, cc2, a0->z); a0->w = fmaf(wv.x, dd, a0->w);
                    float4* a1 = &acc[jv*4 + 1];
                    a1->x = fmaf(wv.y, a, a1->x);  a1->y = fmaf(wv.y, bb2, a1->y);
                    a1->z = fmaf(wv.y, cc2, a1->z); a1->w = fmaf(wv.y, dd, a1->w);
                    float4* a2 = &acc[jv*4 + 2];
                    a2->x = fmaf(wv.z, a, a2->x);  a2->y = fmaf(wv.z, bb2, a2->y);
                    a2->z = fmaf(wv.z, cc2, a2->z); a2->w = fmaf(wv.z, dd, a2->w);
                    float4* a3 = &acc[jv*4 + 3];
                    a3->x = fmaf(wv.w, a, a3->x);  a3->y = fmaf(wv.w, bb2, a3->y);
                    a3->z = fmaf(wv.w, cc2, a3->z); a3->w = fmaf(wv.w, dd, a3->w);
                }
            }
        }
    }

    float* dst = g_part + (((size_t)chunk * BB + b) * JJ) * HWT + (row0 + trow) * WW + tc4;
#pragma unroll
    for (int j = 0; j < JJ; j++)
        *(float4*)(dst + (size_t)j * HWT) = acc[j];
}

// ---------------------------------------------------------------------------
// Kernel 3b: reduce partials over 8 chunks + bias -> g_om
// ---------------------------------------------------------------------------
__global__ __launch_bounds__(256) void reduce_om(const float* __restrict__ omb) {
    int i = blockIdx.x * 256 + threadIdx.x;
    if (i >= BB * JJ * (HWT / 4)) return;
    int p4 = i & 1023;
    int j = (i >> 10) % JJ;
    int b = i / (JJ * 1024);
    float bias = omb[j];
    float4 s = make_float4(bias, bias, bias, bias);
#pragma unroll
    for (int ch = 0; ch < 8; ch++) {
        float4 v = ((const float4*)g_part)[(((size_t)ch * BB + b) * JJ + j) * 1024 + p4];
        s.x += v.x; s.y += v.y; s.z += v.z; s.w += v.w;
    }
    ((float4*)g_om)[(((size_t)b) * JJ + j) * 1024 + p4] = s;
}

// ---------------------------------------------------------------------------
// Kernel 4: deformable conv. Block = (b, 8x16 px tile) -> 64o x 128px.
// Per k: (A) per-px bilinear metadata -> smem, (B) coalesced sampling
// (warp lanes span channels: 4 lines/LDG128) + swizzled STS to s_samp[c][px],
// (C) outer-product GEMM 8o x 4px per thread, weights via warp-uniform LDG.
// ---------------------------------------------------------------------------
__global__ __launch_bounds__(256, 2) void deform(float* __restrict__ out) {
    int bi = blockIdx.x;            // 256 blocks: b(8) x tY(8) x tX(4)
    int b  = bi >> 5;
    int tY = (bi >> 2) & 7;
    int tX = bi & 3;

    __shared__ float4 s_sv[CC * 32];   // swizzled [c][px] samples, 32KB
    __shared__ int4   s_pq[128];       // clamped corner base indices (y*64+x)
    __shared__ float4 s_wq[128];       // corner weights (mask+validity folded)

    int t = threadIdx.x;
    float4 acc8[8];                    // 8 o x 4 px
#pragma unroll
    for (int i = 0; i < 8; i++) acc8[i] = make_float4(0.f, 0.f, 0.f, 0.f);

    const float* omb_ = g_om + (size_t)b * JJ * HWT;
    const float4* imgf4 = (const float4*)(g_nhwc + (size_t)b * HWT * CC);

    int cg4 = t & 15, px8 = t >> 4;    // sampling mapping
    int o8 = t >> 5, sidx = t & 31;    // GEMM mapping

    for (int k = 0; k < 9; k++) {
        // ---- Stage A: per-pixel bilinear metadata ----
        if (t < 128) {
            int gy = tY * 8 + (t >> 4), gx = tX * 16 + (t & 15);
            int p = gy * WW + gx;
            float dy = omb_[(2 * k) * HWT + p];
            float dx = omb_[(2 * k + 1) * HWT + p];
            float mv = omb_[(18 + k) * HWT + p];
            float m = 1.f / (1.f + __expf(-mv));
            float y = (float)(gy - 1 + k / 3) + dy;
            float x = (float)(gx - 1 + k % 3) + dx;
            float yf = floorf(y), xf = floorf(x);
            int yi = (int)yf, xi = (int)xf;
            float wy = y - yf, wx = x - xf;
            bool vy0 = (yi >= 0) && (yi < HH);
            bool vy1 = (yi >= -1) && (yi < HH - 1);
            bool vx0 = (xi >= 0) && (xi < WW);
            bool vx1 = (xi >= -1) && (xi < WW - 1);
            float w00 = (vy0 && vx0) ? (1.f - wy) * (1.f - wx) * m : 0.f;
            float w01 = (vy0 && vx1) ? (1.f - wy) * wx * m : 0.f;
            float w10 = (vy1 && vx0) ? wy * (1.f - wx) * m : 0.f;
            float w11 = (vy1 && vx1) ? wy * wx * m : 0.f;
            int y0c = min(max(yi, 0), HH - 1), y1c = min(max(yi + 1, 0), HH - 1);
            int x0c = min(max(xi, 0), WW - 1), x1c = min(max(xi + 1, 0), WW - 1);
            s_pq[t] = make_int4(y0c * WW + x0c, y0c * WW + x1c,
                                y1c * WW + x0c, y1c * WW + x1c);
            s_wq[t] = make_float4(w00, w01, w10, w11);
        }
        __syncthreads();

        // ---- Stage B: sampling (coalesced over channels) + swizzled STS ----
        {
            float a[8][4];
#pragma unroll
            for (int j = 0; j < 8; j++)
#pragma unroll
                for (int q = 0; q < 4; q++) a[j][q] = 0.f;

#pragma unroll
            for (int j = 0; j < 8; j++) {
                int px = px8 * 8 + j;
                int4 pq = s_pq[px];
                float4 wq = s_wq[px];
                float4 v;
                v = imgf4[pq.x * 16 + cg4];
                a[j][0] = fmaf(wq.x, v.x, a[j][0]); a[j][1] = fmaf(wq.x, v.y, a[j][1]);
                a[j][2] = fmaf(wq.x, v.z, a[j][2]); a[j][3] = fmaf(wq.x, v.w, a[j][3]);
                v = imgf4[pq.y * 16 + cg4];
                a[j][0] = fmaf(wq.y, v.x, a[j][0]); a[j][1] = fmaf(wq.y, v.y, a[j][1]);
                a[j][2] = fmaf(wq.y, v.z, a[j][2]); a[j][3] = fmaf(wq.y, v.w, a[j][3]);
                v = imgf4[pq.z * 16 + cg4];
                a[j][0] = fmaf(wq.z, v.x, a[j][0]); a[j][1] = fmaf(wq.z, v.y, a[j][1]);
                a[j][2] = fmaf(wq.z, v.z, a[j][2]); a[j][3] = fmaf(wq.z, v.w, a[j][3]);
                v = imgf4[pq.w * 16 + cg4];
                a[j][0] = fmaf(wq.w, v.x, a[j][0]); a[j][1] = fmaf(wq.w, v.y, a[j][1]);
                a[j][2] = fmaf(wq.w, v.z, a[j][2]); a[j][3] = fmaf(wq.w, v.w, a[j][3]);
            }
            // register-transposed stores: float4 over px, swizzled columns
#pragma unroll
            for (int q = 0; q < 4; q++) {
                int c = cg4 * 4 + q;
                s_sv[c * 32 + (((px8 * 2) ^ cg4) & 31)] =
                    make_float4(a[0][q], a[1][q], a[2][q], a[3][q]);
                s_sv[c * 32 + (((px8 * 2 + 1) ^ cg4) & 31)] =
                    make_float4(a[4][q], a[5][q], a[6][q], a[7][q]);
            }
        }
        __syncthreads();

        // ---- Stage C: outer-product GEMM (weights via warp-uniform LDG) ----
        {
            const float4* wt4 = (const float4*)(g_wt + k * 4096); // [c][o]
#pragma unroll 16
            for (int c = 0; c < CC; c++) {
                float4 w0 = __ldg(&wt4[c * 16 + o8 * 2]);
                float4 w1 = __ldg(&wt4[c * 16 + o8 * 2 + 1]);
                float4 sv = s_sv[c * 32 + ((sidx ^ (c >> 2)) & 31)];
                acc8[0].x = fmaf(w0.x, sv.x, acc8[0].x); acc8[0].y = fmaf(w0.x, sv.y, acc8[0].y);
                acc8[0].z = fmaf(w0.x, sv.z, acc8[0].z); acc8[0].w = fmaf(w0.x, sv.w, acc8[0].w);
                acc8[1].x = fmaf(w0.y, sv.x, acc8[1].x); acc8[1].y = fmaf(w0.y, sv.y, acc8[1].y);
                acc8[1].z = fmaf(w0.y, sv.z, acc8[1].z); acc8[1].w = fmaf(w0.y, sv.w, acc8[1].w);
                acc8[2].x = fmaf(w0.z, sv.x, acc8[2].x); acc8[2].y = fmaf(w0.z, sv.y, acc8[2].y);
                acc8[2].z = fmaf(w0.z, sv.z, acc8[2].z); acc8[2].w = fmaf(w0.z, sv.w, acc8[2].w);
                acc8[3].x = fmaf(w0.w, sv.x, acc8[3].x); acc8[3].y = fmaf(w0.w, sv.y, acc8[3].y);
                acc8[3].z = fmaf(w0.w, sv.z, acc8[3].z); acc8[3].w = fmaf(w0.w, sv.w, acc8[3].w);
                acc8[4].x = fmaf(w1.x, sv.x, acc8[4].x); acc8[4].y = fmaf(w1.x, sv.y, acc8[4].y);
                acc8[4].z = fmaf(w1.x, sv.z, acc8[4].z); acc8[4].w = fmaf(w1.x, sv.w, acc8[4].w);
                acc8[5].x = fmaf(w1.y, sv.x, acc8[5].x); acc8[5].y = fmaf(w1.y, sv.y, acc8[5].y);
                acc8[5].z = fmaf(w1.y, sv.z, acc8[5].z); acc8[5].w = fmaf(w1.y, sv.w, acc8[5].w);
                acc8[6].x = fmaf(w1.z, sv.x, acc8[6].x); acc8[6].y = fmaf(w1.z, sv.y, acc8[6].y);
                acc8[6].z = fmaf(w1.z, sv.z, acc8[6].z); acc8[6].w = fmaf(w1.z, sv.w, acc8[6].w);
                acc8[7].x = fmaf(w1.w, sv.x, acc8[7].x); acc8[7].y = fmaf(w1.w, sv.y, acc8[7].y);
                acc8[7].z = fmaf(w1.w, sv.z, acc8[7].z); acc8[7].w = fmaf(w1.w, sv.w, acc8[7].w);
            }
        }
        __syncthreads();
    }

    // Writeback (B,O,H,W): 4 consecutive cols in one row -> float4 store
    int px4 = sidx * 4;
    int gy = tY * 8 + (px4 >> 4);
    int gx = tX * 16 + (px4 & 15);
#pragma unroll
    for (int oi = 0; oi < 8; oi++) {
        int o = o8 * 8 + oi;
        *(float4*)(out + (((size_t)b * OO + o) * HH + gy) * WW + gx) = acc8[oi];
    }
}

// ---------------------------------------------------------------------------
extern "C" void kernel_launch(void* const* d_in, const int* in_sizes, int n_in,
                              void* d_out, int out_size) {
    const float* input_feat = (const float*)d_in[0];
    const float* degrad     = (const float*)d_in[1];
    const float* weight     = (const float*)d_in[2];
    const float* om_weight  = (const float*)d_in[3];
    const float* om_bias    = (const float*)d_in[4];
    float* out = (float*)d_out;

    transpose_nhwc<<<BB * HH, 256>>>(input_feat);
    transpose_w<<<(9 * CC * OO + 255) / 256, 256>>>(weight);
    om_conv<<<dim3(64, 8), 128>>>(input_feat, degrad, om_weight);
    reduce_om<<<(BB * JJ * (HWT / 4) + 255) / 256, 256>>>(om_bias);
    deform<<<BB * 32, 256>>>(out);
}

// round 4
// speedup vs baseline: 1.7014x; 1.0521x over previous
#include <cuda_runtime.h>

#define BB 8
#define CC 64
#define HH 64
#define WW 64
#define OO 64
#define HWT (HH*WW)
#define JJ 27
#define JP 28   // padded j for float4/f32x2 weight rows

typedef unsigned long long u64;

// ---- f32x2 packed-FMA helpers (sm_103a FFMA2, PTX-only) ----
__device__ __forceinline__ u64 pk2(float a, float b) {
    u64 r;
    asm("mov.b64 %0, {%1, %2};" : "=l"(r) : "f"(a), "f"(b));
    return r;
}
__device__ __forceinline__ u64 f2fma(u64 a, u64 b, u64 c) {
    u64 d;
    asm("fma.rn.f32x2 %0, %1, %2, %3;" : "=l"(d) : "l"(a), "l"(b), "l"(c));
    return d;
}
__device__ __forceinline__ float2 upk(u64 v) {
    float2 r;
    asm("mov.b64 {%0, %1}, %2;" : "=f"(r.x), "=f"(r.y) : "l"(v));
    return r;
}

// Scratch (device globals: no allocation allowed)
__device__ float g_nhwc[BB*HH*WW*CC];        // input_feat in NHWC
__device__ float g_om[BB*JJ*HWT];            // offset/mask conv output (B,27,H,W)
__device__ float g_wt[9*CC*OO];              // weight transposed to [k][c][o]
__device__ float g_part[8*BB*JJ*HWT];        // om partial sums per channel-chunk

// ---------------------------------------------------------------------------
// Kernel 1: NCHW -> NHWC transpose of input_feat. One block per (b,h).
// ---------------------------------------------------------------------------
__global__ __launch_bounds__(256) void transpose_nhwc(const float* __restrict__ in) {
    int bh = blockIdx.x;
    int b = bh / HH, h = bh % HH;
    __shared__ float tile[CC][WW + 1];
    const float* src = in + ((size_t)b*CC)*HWT + (size_t)h*WW;
    for (int i = threadIdx.x; i < CC*WW; i += 256) {
        int c = i >> 6, w = i & 63;
        tile[c][w] = src[(size_t)c*HWT + w];
    }
    __syncthreads();
    float* dst = g_nhwc + (((size_t)b*HH + h)*WW)*CC;
    for (int i = threadIdx.x; i < CC*WW; i += 256) {
        int w = i >> 6, c = i & 63;
        dst[w*CC + c] = tile[c][w];
    }
}

// ---------------------------------------------------------------------------
// Kernel 2: weight (O,C,3,3) -> g_wt[k][c][o]
// ---------------------------------------------------------------------------
__global__ void transpose_w(const float* __restrict__ w) {
    int i = blockIdx.x * blockDim.x + threadIdx.x;
    if (i < 9*CC*OO) {
        int k = i / (CC*OO);
        int r = i % (CC*OO);
        int c = r >> 6;
        int o = r & 63;
        g_wt[i] = w[(o*CC + c)*9 + k];
    }
}

// ---------------------------------------------------------------------------
// Kernel 3: om partial conv, f32x2 packed over j (weight pairs contiguous).
// Block = (spatial 8 rows x 64 cols, 16-ch chunk), 128 threads, 4 px/thread.
// ---------------------------------------------------------------------------
__global__ __launch_bounds__(128, 3) void om_conv(const float* __restrict__ feat,
                                                  const float* __restrict__ deg,
                                                  const float* __restrict__ omw) {
    int chunk = blockIdx.y;
    int sb = blockIdx.x;
    int b = sb >> 3;
    int row0 = (sb & 7) * 8;

    __shared__ float s_in[16 * 10 * 66];
    __shared__ float s_w[16 * 9 * JP];

    int t = threadIdx.x;

    for (int i = t; i < 16 * 9 * JP; i += 128) {
        int j = i % JP;
        int tap = (i / JP) % 9;
        int ci = i / (9 * JP);
        s_w[i] = (j < JJ) ? omw[(j * 128 + chunk * 16 + ci) * 9 + tap] : 0.f;
    }
    for (int i = t; i < 16 * 660; i += 128) {
        int ci = i / 660;
        int r = i % 660;
        int yy = r / 66 + row0 - 1;
        int xx = r % 66 - 1;
        float v = 0.f;
        if (yy >= 0 && yy < HH && xx >= 0 && xx < WW) {
            int gc = chunk * 16 + ci;
            const float* src = (gc < CC) ? feat : deg;
            v = src[(((size_t)b * CC + (gc & 63)) * HH + yy) * WW + xx];
        }
        s_in[i] = v;
    }
    __syncthreads();

    int trow = t >> 4;
    int tc4 = (t & 15) * 4;

    // acc2[jpair][px]: (j_even, j_odd) packed, 14 pairs x 4 px
    u64 acc2[14][4];
#pragma unroll
    for (int jp = 0; jp < 14; jp++)
#pragma unroll
        for (int p = 0; p < 4; p++) acc2[jp][p] = 0ULL;

    for (int ci = 0; ci < 16; ci++) {
        const float* bi = s_in + ci * 660 + trow * 66 + tc4;
        const float* bw = s_w + ci * 9 * JP;
#pragma unroll
        for (int ky = 0; ky < 3; ky++) {
            float v0 = bi[ky*66 + 0], v1 = bi[ky*66 + 1], v2 = bi[ky*66 + 2];
            float v3 = bi[ky*66 + 3], v4 = bi[ky*66 + 4], v5 = bi[ky*66 + 5];
#pragma unroll
            for (int kx = 0; kx < 3; kx++) {
                float a = (kx == 0) ? v0 : (kx == 1) ? v1 : v2;
                float bb2 = (kx == 0) ? v1 : (kx == 1) ? v2 : v3;
                float cc2 = (kx == 0) ? v2 : (kx == 1) ? v3 : v4;
                float dd = (kx == 0) ? v3 : (kx == 1) ? v4 : v5;
                u64 vd[4];
                vd[0] = pk2(a, a);  vd[1] = pk2(bb2, bb2);
                vd[2] = pk2(cc2, cc2); vd[3] = pk2(dd, dd);
                const ulonglong2* wr = (const ulonglong2*)(bw + (ky * 3 + kx) * JP);
#pragma unroll
                for (int jv = 0; jv < 7; jv++) {
                    ulonglong2 wp = wr[jv];
#pragma unroll
                    for (int p = 0; p < 4; p++)
                        acc2[jv*2 + 0][p] = f2fma(wp.x, vd[p], acc2[jv*2 + 0][p]);
#pragma unroll
                    for (int p = 0; p < 4; p++)
                        acc2[jv*2 + 1][p] = f2fma(wp.y, vd[p], acc2[jv*2 + 1][p]);
                }
            }
        }
    }

    // Unpack + store partials: g_part[chunk][b][j][p]
    float* dst = g_part + (((size_t)chunk * BB + b) * JJ) * HWT + (row0 + trow) * WW + tc4;
#pragma unroll
    for (int jp = 0; jp < 14; jp++) {
        float2 p0 = upk(acc2[jp][0]), p1 = upk(acc2[jp][1]);
        float2 p2 = upk(acc2[jp][2]), p3 = upk(acc2[jp][3]);
        int j0 = jp * 2;
        *(float4*)(dst + (size_t)j0 * HWT) = make_float4(p0.x, p1.x, p2.x, p3.x);
        if (j0 + 1 < JJ)
            *(float4*)(dst + (size_t)(j0 + 1) * HWT) = make_float4(p0.y, p1.y, p2.y, p3.y);
    }
}

// ---------------------------------------------------------------------------
// Kernel 3b: reduce partials over 8 chunks + bias -> g_om
// ---------------------------------------------------------------------------
__global__ __launch_bounds__(256) void reduce_om(const float* __restrict__ omb) {
    int i = blockIdx.x * 256 + threadIdx.x;
    if (i >= BB * JJ * (HWT / 4)) return;
    int p4 = i & 1023;
    int j = (i >> 10) % JJ;
    int b = i / (JJ * 1024);
    float bias = omb[j];
    float4 s = make_float4(bias, bias, bias, bias);
#pragma unroll
    for (int ch = 0; ch < 8; ch++) {
        float4 v = ((const float4*)g_part)[(((size_t)ch * BB + b) * JJ + j) * 1024 + p4];
        s.x += v.x; s.y += v.y; s.z += v.z; s.w += v.w;
    }
    ((float4*)g_om)[(((size_t)b) * JJ + j) * 1024 + p4] = s;
}

// ---------------------------------------------------------------------------
// Kernel 4: deformable conv. Block = (b, 8x16 px tile) -> 64o x 128px.
// Stage B: coalesced bilinear sampling (lanes span channels) + swizzled STS.
// Stage C: f32x2 GEMM packed over o (weight o-pairs contiguous in g_wt).
// ---------------------------------------------------------------------------
__global__ __launch_bounds__(256, 2) void deform(float* __restrict__ out) {
    int bi = blockIdx.x;            // 256 blocks: b(8) x tY(8) x tX(4)
    int b  = bi >> 5;
    int tY = (bi >> 2) & 7;
    int tX = bi & 3;

    __shared__ float4 s_sv[CC * 32];   // swizzled [c][px] samples, 32KB
    __shared__ int4   s_pq[128];       // clamped corner base indices (y*64+x)
    __shared__ float4 s_wq[128];       // corner weights (mask+validity folded)

    int t = threadIdx.x;
    u64 acc2[4][4];                    // [o-pair][px]
#pragma unroll
    for (int i = 0; i < 4; i++)
#pragma unroll
        for (int j = 0; j < 4; j++) acc2[i][j] = 0ULL;

    const float* omb_ = g_om + (size_t)b * JJ * HWT;
    const float4* imgf4 = (const float4*)(g_nhwc + (size_t)b * HWT * CC);

    int cg4 = t & 15, px8 = t >> 4;    // sampling mapping
    int o8 = t >> 5, sidx = t & 31;    // GEMM mapping

    for (int k = 0; k < 9; k++) {
        // ---- Stage A: per-pixel bilinear metadata ----
        if (t < 128) {
            int gy = tY * 8 + (t >> 4), gx = tX * 16 + (t & 15);
            int p = gy * WW + gx;
            float dy = omb_[(2 * k) * HWT + p];
            float dx = omb_[(2 * k + 1) * HWT + p];
            float mv = omb_[(18 + k) * HWT + p];
            float m = 1.f / (1.f + __expf(-mv));
            float y = (float)(gy - 1 + k / 3) + dy;
            float x = (float)(gx - 1 + k % 3) + dx;
            float yf = floorf(y), xf = floorf(x);
            int yi = (int)yf, xi = (int)xf;
            float wy = y - yf, wx = x - xf;
            bool vy0 = (yi >= 0) && (yi < HH);
            bool vy1 = (yi >= -1) && (yi < HH - 1);
            bool vx0 = (xi >= 0) && (xi < WW);
            bool vx1 = (xi >= -1) && (xi < WW - 1);
            float w00 = (vy0 && vx0) ? (1.f - wy) * (1.f - wx) * m : 0.f;
            float w01 = (vy0 && vx1) ? (1.f - wy) * wx * m : 0.f;
            float w10 = (vy1 && vx0) ? wy * (1.f - wx) * m : 0.f;
            float w11 = (vy1 && vx1) ? wy * wx * m : 0.f;
            int y0c = min(max(yi, 0), HH - 1), y1c = min(max(yi + 1, 0), HH - 1);
            int x0c = min(max(xi, 0), WW - 1), x1c = min(max(xi + 1, 0), WW - 1);
            s_pq[t] = make_int4(y0c * WW + x0c, y0c * WW + x1c,
                                y1c * WW + x0c, y1c * WW + x1c);
            s_wq[t] = make_float4(w00, w01, w10, w11);
        }
        __syncthreads();

        // ---- Stage B: sampling (coalesced over channels) + swizzled STS ----
        {
            float a[8][4];
#pragma unroll
            for (int j = 0; j < 8; j++)
#pragma unroll
                for (int q = 0; q < 4; q++) a[j][q] = 0.f;

#pragma unroll
            for (int j = 0; j < 8; j++) {
                int px = px8 * 8 + j;
                int4 pq = s_pq[px];
                float4 wq = s_wq[px];
                float4 v;
                v = imgf4[pq.x * 16 + cg4];
                a[j][0] = fmaf(wq.x, v.x, a[j][0]); a[j][1] = fmaf(wq.x, v.y, a[j][1]);
                a[j][2] = fmaf(wq.x, v.z, a[j][2]); a[j][3] = fmaf(wq.x, v.w, a[j][3]);
                v = imgf4[pq.y * 16 + cg4];
                a[j][0] = fmaf(wq.y, v.x, a[j][0]); a[j][1] = fmaf(wq.y, v.y, a[j][1]);
                a[j][2] = fmaf(wq.y, v.z, a[j][2]); a[j][3] = fmaf(wq.y, v.w, a[j][3]);
                v = imgf4[pq.z * 16 + cg4];
                a[j][0] = fmaf(wq.z, v.x, a[j][0]); a[j][1] = fmaf(wq.z, v.y, a[j][1]);
                a[j][2] = fmaf(wq.z, v.z, a[j][2]); a[j][3] = fmaf(wq.z, v.w, a[j][3]);
                v = imgf4[pq.w * 16 + cg4];
                a[j][0] = fmaf(wq.w, v.x, a[j][0]); a[j][1] = fmaf(wq.w, v.y, a[j][1]);
                a[j][2] = fmaf(wq.w, v.z, a[j][2]); a[j][3] = fmaf(wq.w, v.w, a[j][3]);
            }
#pragma unroll
            for (int q = 0; q < 4; q++) {
                int c = cg4 * 4 + q;
                s_sv[c * 32 + (((px8 * 2) ^ cg4) & 31)] =
                    make_float4(a[0][q], a[1][q], a[2][q], a[3][q]);
                s_sv[c * 32 + (((px8 * 2 + 1) ^ cg4) & 31)] =
                    make_float4(a[4][q], a[5][q], a[6][q], a[7][q]);
            }
        }
        __syncthreads();

        // ---- Stage C: f32x2 outer-product GEMM (o-pairs packed) ----
        {
            const ulonglong2* wt2 = (const ulonglong2*)(g_wt + k * 4096); // [c][o]
#pragma unroll 16
            for (int c = 0; c < CC; c++) {
                ulonglong2 wa = __ldg(&wt2[c * 16 + o8 * 2]);      // o pairs 0,1
                ulonglong2 wb = __ldg(&wt2[c * 16 + o8 * 2 + 1]);  // o pairs 2,3
                float4 sv = s_sv[c * 32 + ((sidx ^ (c >> 2)) & 31)];
                u64 s0 = pk2(sv.x, sv.x), s1 = pk2(sv.y, sv.y);
                u64 s2 = pk2(sv.z, sv.z), s3 = pk2(sv.w, sv.w);
                acc2[0][0] = f2fma(wa.x, s0, acc2[0][0]);
                acc2[0][1] = f2fma(wa.x, s1, acc2[0][1]);
                acc2[0][2] = f2fma(wa.x, s2, acc2[0][2]);
                acc2[0][3] = f2fma(wa.x, s3, acc2[0][3]);
                acc2[1][0] = f2fma(wa.y, s0, acc2[1][0]);
                acc2[1][1] = f2fma(wa.y, s1, acc2[1][1]);
                acc2[1][2] = f2fma(wa.y, s2, acc2[1][2]);
                acc2[1][3] = f2fma(wa.y, s3, acc2[1][3]);
                acc2[2][0] = f2fma(wb.x, s0, acc2[2][0]);
                acc2[2][1] = f2fma(wb.x, s1, acc2[2][1]);
                acc2[2][2] = f2fma(wb.x, s2, acc2[2][2]);
                acc2[2][3] = f2fma(wb.x, s3, acc2[2][3]);
                acc2[3][0] = f2fma(wb.y, s0, acc2[3][0]);
                acc2[3][1] = f2fma(wb.y, s1, acc2[3][1]);
                acc2[3][2] = f2fma(wb.y, s2, acc2[3][2]);
                acc2[3][3] = f2fma(wb.y, s3, acc2[3][3]);
            }
        }
        __syncthreads();
    }

    // Writeback (B,O,H,W): unpack o-pairs, float4 over px per o
    int px4 = sidx * 4;
    int gy = tY * 8 + (px4 >> 4);
    int gx = tX * 16 + (px4 & 15);
#pragma unroll
    for (int op = 0; op < 4; op++) {
        float2 p0 = upk(acc2[op][0]), p1 = upk(acc2[op][1]);
        float2 p2 = upk(acc2[op][2]), p3 = upk(acc2[op][3]);
        int oe = o8 * 8 + op * 2;
        *(float4*)(out + (((size_t)b * OO + oe) * HH + gy) * WW + gx) =
            make_float4(p0.x, p1.x, p2.x, p3.x);
        *(float4*)(out + (((size_t)b * OO + oe + 1) * HH + gy) * WW + gx) =
            make_float4(p0.y, p1.y, p2.y, p3.y);
    }
}

// ---------------------------------------------------------------------------
extern "C" void kernel_launch(void* const* d_in, const int* in_sizes, int n_in,
                              void* d_out, int out_size) {
    const float* input_feat = (const float*)d_in[0];
    const float* degrad     = (const float*)d_in[1];
    const float* weight     = (const float*)d_in[2];
    const float* om_weight  = (const float*)d_in[3];
    const float* om_bias    = (const float*)d_in[4];
    float* out = (float*)d_out;

    transpose_nhwc<<<BB * HH, 256>>>(input_feat);
    transpose_w<<<(9 * CC * OO + 255) / 256, 256>>>(weight);
    om_conv<<<dim3(64, 8), 128>>>(input_feat, degrad, om_weight);
    reduce_om<<<(BB * JJ * (HWT / 4) + 255) / 256, 256>>>(om_bias);
    deform<<<BB * 32, 256>>>(out);
}

// round 7
// speedup vs baseline: 1.8584x; 1.0923x over previous
#include <cuda_runtime.h>
#include <cstdint>

#define BB 8
#define CC 64
#define HH 64
#define WW 64
#define OO 64
#define HWT (HH*WW)
#define JJ 27
#define JP 28

typedef unsigned long long u64;

// ---- f32x2 packed-FMA helpers (om_conv) ----
__device__ __forceinline__ u64 pk2(float a, float b) {
    u64 r;
    asm("mov.b64 %0, {%1, %2};" : "=l"(r) : "f"(a), "f"(b));
    return r;
}
__device__ __forceinline__ u64 f2fma(u64 a, u64 b, u64 c) {
    u64 d;
    asm("fma.rn.f32x2 %0, %1, %2, %3;" : "=l"(d) : "l"(a), "l"(b), "l"(c));
    return d;
}
__device__ __forceinline__ float2 upk(u64 v) {
    float2 r;
    asm("mov.b64 {%0, %1}, %2;" : "=f"(r.x), "=f"(r.y) : "l"(v));
    return r;
}
// tf32 round (keeps top 10 mantissa bits)
__device__ __forceinline__ float tf32r(float x) {
    unsigned u;
    asm("cvt.rna.tf32.f32 %0, %1;" : "=r"(u) : "f"(x));
    return __uint_as_float(u);
}

// mma.sync m16n8k8 tf32: D += A*B (fp32 accum)
#define MMA8(D, A0, A1, A2, A3, B0, B1)                                   \
    asm volatile("mma.sync.aligned.m16n8k8.row.col.f32.tf32.tf32.f32 "     \
        "{%0,%1,%2,%3}, {%4,%5,%6,%7}, {%8,%9}, {%0,%1,%2,%3};"            \
        : "+f"((D)[0]), "+f"((D)[1]), "+f"((D)[2]), "+f"((D)[3])           \
        : "r"(A0), "r"(A1), "r"(A2), "r"(A3), "r"(B0), "r"(B1))

// Scratch (device globals: no allocation allowed)
__device__ float  g_nhwc[BB*HH*WW*CC];    // input_feat NHWC
__device__ float  g_om[BB*JJ*HWT];        // offset/mask conv output
__device__ __align__(16) float2 g_wtB[9*2*2048];  // deform weights, B-frag layout
__device__ float  g_part[8*BB*JJ*HWT];    // om partials

// ---------------------------------------------------------------------------
// Kernel 1: NCHW -> NHWC transpose of input_feat.
// ---------------------------------------------------------------------------
__global__ __launch_bounds__(256) void transpose_nhwc(const float* __restrict__ in) {
    int bh = blockIdx.x;
    int b = bh / HH, h = bh % HH;
    __shared__ float tile[CC][WW + 1];
    const float* src = in + ((size_t)b*CC)*HWT + (size_t)h*WW;
    for (int i = threadIdx.x; i < CC*WW; i += 256) {
        int c = i >> 6, w = i & 63;
        tile[c][w] = src[(size_t)c*HWT + w];
    }
    __syncthreads();
    float* dst = g_nhwc + (((size_t)b*HH + h)*WW)*CC;
    for (int i = threadIdx.x; i < CC*WW; i += 256) {
        int w = i >> 6, c = i & 63;
        dst[w*CC + c] = tile[c][w];
    }
}

// ---------------------------------------------------------------------------
// Kernel 2: weight (O,C,3,3) -> g_wtB in m16n8k8 B-fragment layout, hi/lo tf32.
// Channel perm within 8-chunk: k-pos kk holds channel 2*(kk&3)+(kk>>2), so
// (b0,b1) = consecutive channels.
// ---------------------------------------------------------------------------
__global__ void transpose_w(const float* __restrict__ w) {
    int i = blockIdx.x * blockDim.x + threadIdx.x;
    if (i >= 9*2*2048) return;
    int k = i / 4096;
    int r = i % 4096;
    int h = r >> 11;
    int e = r & 2047;
    int lane = e & 31;
    int frag = e >> 5;          // s*8 + nt
    int nt = frag & 7, s = frag >> 3;
    int o = nt*8 + (lane >> 2);
    int c0 = s*8 + (lane & 3)*2;
    float v0 = w[(o*CC + c0)*9 + k];
    float v1 = w[(o*CC + c0 + 1)*9 + k];
    float h0 = tf32r(v0), h1 = tf32r(v1);
    g_wtB[i] = h ? make_float2(tf32r(v0 - h0), tf32r(v1 - h1))
                 : make_float2(h0, h1);
}

// ---------------------------------------------------------------------------
// Kernel 3: om partial conv (FFMA2, unchanged).
// ---------------------------------------------------------------------------
__global__ __launch_bounds__(128, 3) void om_conv(const float* __restrict__ feat,
                                                  const float* __restrict__ deg,
                                                  const float* __restrict__ omw) {
    int chunk = blockIdx.y;
    int sb = blockIdx.x;
    int b = sb >> 3;
    int row0 = (sb & 7) * 8;

    __shared__ float s_in[16 * 10 * 66];
    __shared__ float s_w[16 * 9 * JP];

    int t = threadIdx.x;

    for (int i = t; i < 16 * 9 * JP; i += 128) {
        int j = i % JP;
        int tap = (i / JP) % 9;
        int ci = i / (9 * JP);
        s_w[i] = (j < JJ) ? omw[(j * 128 + chunk * 16 + ci) * 9 + tap] : 0.f;
    }
    for (int i = t; i < 16 * 660; i += 128) {
        int ci = i / 660;
        int r = i % 660;
        int yy = r / 66 + row0 - 1;
        int xx = r % 66 - 1;
        float v = 0.f;
        if (yy >= 0 && yy < HH && xx >= 0 && xx < WW) {
            int gc = chunk * 16 + ci;
            const float* src = (gc < CC) ? feat : deg;
            v = src[(((size_t)b * CC + (gc & 63)) * HH + yy) * WW + xx];
        }
        s_in[i] = v;
    }
    __syncthreads();

    int trow = t >> 4;
    int tc4 = (t & 15) * 4;

    u64 acc2[14][4];
#pragma unroll
    for (int jp = 0; jp < 14; jp++)
#pragma unroll
        for (int p = 0; p < 4; p++) acc2[jp][p] = 0ULL;

    for (int ci = 0; ci < 16; ci++) {
        const float* bi = s_in + ci * 660 + trow * 66 + tc4;
        const float* bw = s_w + ci * 9 * JP;
#pragma unroll
        for (int ky = 0; ky < 3; ky++) {
            float v0 = bi[ky*66 + 0], v1 = bi[ky*66 + 1], v2 = bi[ky*66 + 2];
            float v3 = bi[ky*66 + 3], v4 = bi[ky*66 + 4], v5 = bi[ky*66 + 5];
#pragma unroll
            for (int kx = 0; kx < 3; kx++) {
                float a = (kx == 0) ? v0 : (kx == 1) ? v1 : v2;
                float bb2 = (kx == 0) ? v1 : (kx == 1) ? v2 : v3;
                float cc2 = (kx == 0) ? v2 : (kx == 1) ? v3 : v4;
                float dd = (kx == 0) ? v3 : (kx == 1) ? v4 : v5;
                u64 vd[4];
                vd[0] = pk2(a, a);  vd[1] = pk2(bb2, bb2);
                vd[2] = pk2(cc2, cc2); vd[3] = pk2(dd, dd);
                const ulonglong2* wr = (const ulonglong2*)(bw + (ky * 3 + kx) * JP);
#pragma unroll
                for (int jv = 0; jv < 7; jv++) {
                    ulonglong2 wp = wr[jv];
#pragma unroll
                    for (int p = 0; p < 4; p++)
                        acc2[jv*2 + 0][p] = f2fma(wp.x, vd[p], acc2[jv*2 + 0][p]);
#pragma unroll
                    for (int p = 0; p < 4; p++)
                        acc2[jv*2 + 1][p] = f2fma(wp.y, vd[p], acc2[jv*2 + 1][p]);
                }
            }
        }
    }

    float* dst = g_part + (((size_t)chunk * BB + b) * JJ) * HWT + (row0 + trow) * WW + tc4;
#pragma unroll
    for (int jp = 0; jp < 14; jp++) {
        float2 p0 = upk(acc2[jp][0]), p1 = upk(acc2[jp][1]);
        float2 p2 = upk(acc2[jp][2]), p3 = upk(acc2[jp][3]);
        int j0 = jp * 2;
        *(float4*)(dst + (size_t)j0 * HWT) = make_float4(p0.x, p1.x, p2.x, p3.x);
        if (j0 + 1 < JJ)
            *(float4*)(dst + (size_t)(j0 + 1) * HWT) = make_float4(p0.y, p1.y, p2.y, p3.y);
    }
}

// ---------------------------------------------------------------------------
// Kernel 3b: reduce partials + bias -> g_om
// ---------------------------------------------------------------------------
__global__ __launch_bounds__(256) void reduce_om(const float* __restrict__ omb) {
    int i = blockIdx.x * 256 + threadIdx.x;
    if (i >= BB * JJ * (HWT / 4)) return;
    int p4 = i & 1023;
    int j = (i >> 10) % JJ;
    int b = i / (JJ * 1024);
    float bias = omb[j];
    float4 s = make_float4(bias, bias, bias, bias);
#pragma unroll
    for (int ch = 0; ch < 8; ch++) {
        float4 v = ((const float4*)g_part)[(((size_t)ch * BB + b) * JJ + j) * 1024 + p4];
        s.x += v.x; s.y += v.y; s.z += v.z; s.w += v.w;
    }
    ((float4*)g_om)[(((size_t)b) * JJ + j) * 1024 + p4] = s;
}

// ---------------------------------------------------------------------------
// Kernel 4: deformable conv via mma.sync tf32, 3-pass hi/lo split.
// Block = 128px x 64o; warps 4M x 2N (tile 32x32); D in fp32 regs across taps.
// A smem in fragment layout (word order a0,a2,a1,a3; 528B frag stride).
// ---------------------------------------------------------------------------
#define SM_PQ  0
#define SM_WQ  2048
#define SM_AHI 4096
#define SM_ALO (SM_AHI + 33792)
#define SM_B   (SM_ALO + 33792)
#define SM_TOT (SM_B + 32768)

__global__ __launch_bounds__(256) void deform(float* __restrict__ out) {
    extern __shared__ char sm[];
    int bi = blockIdx.x;            // 256 blocks: b(8) x tY(8) x tX(4)
    int b  = bi >> 5;
    int tY = (bi >> 2) & 7;
    int tX = bi & 3;

    int t = threadIdx.x;
    int lane = t & 31;
    int wrp = t >> 5;
    int wm = wrp >> 1, wn = wrp & 1;

    int4*   s_pq = (int4*)(sm + SM_PQ);
    float4* s_wq = (float4*)(sm + SM_WQ);

    const float*  omb_  = g_om + (size_t)b * JJ * HWT;
    const float4* imgf4 = (const float4*)(g_nhwc + (size_t)b * HWT * CC);

    // sampler mapping: q = 4-channel group (0..15), px8 = 8-px group (0..15)
    int q = t & 15, px8 = t >> 4;
    int s_smp = q >> 1;
    int lnc = (q & 1) * 2;

    float d[2][4][4];
#pragma unroll
    for (int i = 0; i < 2; i++)
#pragma unroll
        for (int j = 0; j < 4; j++)
#pragma unroll
            for (int e = 0; e < 4; e++) d[i][j][e] = 0.f;

    for (int k = 0; k < 9; k++) {
        if (k) __syncthreads();     // previous GEMM done reading smem

        // Stage A: per-pixel bilinear metadata
        if (t < 128) {
            int gy = tY * 8 + (t >> 4), gx = tX * 16 + (t & 15);
            int p = gy * WW + gx;
            float dy = omb_[(2 * k) * HWT + p];
            float dx = omb_[(2 * k + 1) * HWT + p];
            float mv = omb_[(18 + k) * HWT + p];
            float m = 1.f / (1.f + __expf(-mv));
            float y = (float)(gy - 1 + k / 3) + dy;
            float x = (float)(gx - 1 + k % 3) + dx;
            float yf = floorf(y), xf = floorf(x);
            int yi = (int)yf, xi = (int)xf;
            float wy = y - yf, wx = x - xf;
            bool vy0 = (yi >= 0) && (yi < HH);
            bool vy1 = (yi >= -1) && (yi < HH - 1);
            bool vx0 = (xi >= 0) && (xi < WW);
            bool vx1 = (xi >= -1) && (xi < WW - 1);
            float w00 = (vy0 && vx0) ? (1.f - wy) * (1.f - wx) * m : 0.f;
            float w01 = (vy0 && vx1) ? (1.f - wy) * wx * m : 0.f;
            float w10 = (vy1 && vx0) ? wy * (1.f - wx) * m : 0.f;
            float w11 = (vy1 && vx1) ? wy * wx * m : 0.f;
            int y0c = min(max(yi, 0), HH - 1), y1c = min(max(yi + 1, 0), HH - 1);
            int x0c = min(max(xi, 0), WW - 1), x1c = min(max(xi + 1, 0), WW - 1);
            s_pq[t] = make_int4(y0c * WW + x0c, y0c * WW + x1c,
                                y1c * WW + x0c, y1c * WW + x1c);
            s_wq[t] = make_float4(w00, w01, w10, w11);
        }
        // B tile copy: FULL 32KB (hi 16KB + lo 16KB)  [R6 bug: only 16KB copied]
        {
            const float4* srcB = (const float4*)(g_wtB + (size_t)k * 4096);
            float4* dstB = (float4*)(sm + SM_B);
#pragma unroll
            for (int i = 0; i < 8; i++) dstB[i * 256 + t] = srcB[i * 256 + t];
        }
        __syncthreads();

        // Stage B: coalesced bilinear sampling + hi/lo split, fragment-layout STS
#pragma unroll
        for (int j = 0; j < 8; j++) {
            int px = px8 * 8 + j;
            int4 pq = s_pq[px];
            float4 wq = s_wq[px];
            float a0 = 0.f, a1 = 0.f, a2 = 0.f, a3 = 0.f;
            float4 v;
            v = imgf4[pq.x * 16 + q];
            a0 = fmaf(wq.x, v.x, a0); a1 = fmaf(wq.x, v.y, a1);
            a2 = fmaf(wq.x, v.z, a2); a3 = fmaf(wq.x, v.w, a3);
            v = imgf4[pq.y * 16 + q];
            a0 = fmaf(wq.y, v.x, a0); a1 = fmaf(wq.y, v.y, a1);
            a2 = fmaf(wq.y, v.z, a2); a3 = fmaf(wq.y, v.w, a3);
            v = imgf4[pq.z * 16 + q];
            a0 = fmaf(wq.z, v.x, a0); a1 = fmaf(wq.z, v.y, a1);
            a2 = fmaf(wq.z, v.z, a2); a3 = fmaf(wq.z, v.w, a3);
            v = imgf4[pq.w * 16 + q];
            a0 = fmaf(wq.w, v.x, a0); a1 = fmaf(wq.w, v.y, a1);
            a2 = fmaf(wq.w, v.z, a2); a3 = fmaf(wq.w, v.w, a3);

            float h0 = tf32r(a0), h1 = tf32r(a1), h2 = tf32r(a2), h3 = tf32r(a3);
            float l0 = tf32r(a0 - h0), l1 = tf32r(a1 - h1);
            float l2 = tf32r(a2 - h2), l3 = tf32r(a3 - h3);

            int mt = px >> 4;
            int r = px & 7;
            int high = (px >> 3) & 1;
            int fo = (mt * 8 + s_smp) * 528 + high * 8;
            int la = (r * 4 + lnc) * 16;
            *(float2*)(sm + SM_AHI + fo + la)      = make_float2(h0, h1);
            *(float2*)(sm + SM_AHI + fo + la + 16) = make_float2(h2, h3);
            *(float2*)(sm + SM_ALO + fo + la)      = make_float2(l0, l1);
            *(float2*)(sm + SM_ALO + fo + la + 16) = make_float2(l2, l3);
        }
        __syncthreads();

        // Stage C: tensor-core GEMM, 3 passes (hh, lh, hl)
        {
            const char* Ah = sm + SM_AHI;
            const char* Al = sm + SM_ALO;
            const char* Bh = sm + SM_B;
            const char* Bl = sm + SM_B + 16384;
#pragma unroll
            for (int s = 0; s < 8; s++) {
                int f0 = ((wm * 2 + 0) * 8 + s) * 528 + lane * 16;
                int f1 = ((wm * 2 + 1) * 8 + s) * 528 + lane * 16;
                uint4 ah0 = *(const uint4*)(Ah + f0);
                uint4 ah1 = *(const uint4*)(Ah + f1);
                uint4 al0 = *(const uint4*)(Al + f0);
                uint4 al1 = *(const uint4*)(Al + f1);
#pragma unroll
                for (int nt = 0; nt < 4; nt++) {
                    int fi = ((s * 8 + wn * 4 + nt) * 32 + lane) * 8;
                    uint2 bh = *(const uint2*)(Bh + fi);
                    uint2 bl = *(const uint2*)(Bl + fi);
                    // memory word order (a0,a2,a1,a3) -> operands {x,z,y,w}
                    MMA8(d[0][nt], ah0.x, ah0.z, ah0.y, ah0.w, bh.x, bh.y);
                    MMA8(d[0][nt], al0.x, al0.z, al0.y, al0.w, bh.x, bh.y);
                    MMA8(d[0][nt], ah0.x, ah0.z, ah0.y, ah0.w, bl.x, bl.y);
                    MMA8(d[1][nt], ah1.x, ah1.z, ah1.y, ah1.w, bh.x, bh.y);
                    MMA8(d[1][nt], al1.x, al1.z, al1.y, al1.w, bh.x, bh.y);
                    MMA8(d[1][nt], ah1.x, ah1.z, ah1.y, ah1.w, bl.x, bl.y);
                }
            }
        }
    }

    // Epilogue: D fragments -> out (B,O,H,W)
#pragma unroll
    for (int mi = 0; mi < 2; mi++) {
        int pxb = (wm * 2 + mi) * 16 + (lane >> 2);
        int gy0 = tY * 8 + (pxb >> 4), gx0 = tX * 16 + (pxb & 15);
        int px2 = pxb + 8;
        int gy1 = tY * 8 + (px2 >> 4), gx1 = tX * 16 + (px2 & 15);
#pragma unroll
        for (int nt = 0; nt < 4; nt++) {
            int o = wn * 32 + nt * 8 + (lane & 3) * 2;
            size_t base = ((size_t)b * OO + o) * HWT;
            out[base + gy0 * WW + gx0]       = d[mi][nt][0];
            out[base + HWT + gy0 * WW + gx0] = d[mi][nt][1];
            out[base + gy1 * WW + gx1]       = d[mi][nt][2];
            out[base + HWT + gy1 * WW + gx1] = d[mi][nt][3];
        }
    }
}

// ---------------------------------------------------------------------------
extern "C" void kernel_launch(void* const* d_in, const int* in_sizes, int n_in,
                              void* d_out, int out_size) {
    const float* input_feat = (const float*)d_in[0];
    const float* degrad     = (const float*)d_in[1];
    const float* weight     = (const float*)d_in[2];
    const float* om_weight  = (const float*)d_in[3];
    const float* om_bias    = (const float*)d_in[4];
    float* out = (float*)d_out;

    cudaFuncSetAttribute(deform, cudaFuncAttributeMaxDynamicSharedMemorySize, SM_TOT);

    transpose_nhwc<<<BB * HH, 256>>>(input_feat);
    transpose_w<<<(9 * 2 * 2048 + 255) / 256, 256>>>(weight);
    om_conv<<<dim3(64, 8), 128>>>(input_feat, degrad, om_weight);
    reduce_om<<<(BB * JJ * (HWT / 4) + 255) / 256, 256>>>(om_bias);
    deform<<<BB * 32, 256, SM_TOT>>>(out);
}

// round 9
// speedup vs baseline: 2.0081x; 1.0806x over previous
#include <cuda_runtime.h>
#include <cstdint>

#define BB 8
#define CC 64
#define HH 64
#define WW 64
#define OO 64
#define HWT (HH*WW)
#define JJ 27

// tf32 round (keeps top 10 mantissa bits)
__device__ __forceinline__ float tf32r(float x) {
    unsigned u;
    asm("cvt.rna.tf32.f32 %0, %1;" : "=r"(u) : "f"(x));
    return __uint_as_float(u);
}

// mma.sync m16n8k8 tf32: D += A*B (fp32 accum)
#define MMA8(D, A0, A1, A2, A3, B0, B1)                                   \
    asm volatile("mma.sync.aligned.m16n8k8.row.col.f32.tf32.tf32.f32 "     \
        "{%0,%1,%2,%3}, {%4,%5,%6,%7}, {%8,%9}, {%0,%1,%2,%3};"            \
        : "+f"((D)[0]), "+f"((D)[1]), "+f"((D)[2]), "+f"((D)[3])           \
        : "r"(A0), "r"(A1), "r"(A2), "r"(A3), "r"(B0), "r"(B1))

// Scratch (device globals: no allocation allowed)
__device__ float  g_nhwc2[BB*HH*WW*128];   // concat(feat, degrad) NHWC, 128 ch
__device__ float  g_om[BB*JJ*HWT];         // offset/mask conv output
__device__ __align__(16) float2 g_wtB[9*2*2048];    // deform weights, B-frag layout
__device__ __align__(16) float2 g_omB[9*2*2*8*4*32]; // om weights  [k][c64][h][s][nt][lane]

// ---------------------------------------------------------------------------
// Kernel 1: NCHW feat+degrad -> g_nhwc2[b][y][x][128]. One block per (b,h).
// ---------------------------------------------------------------------------
__global__ __launch_bounds__(256) void transpose_nhwc2(const float* __restrict__ feat,
                                                       const float* __restrict__ deg) {
    int bh = blockIdx.x;
    int b = bh / HH, h = bh % HH;
    __shared__ float tile[128][WW + 1];
    for (int i = threadIdx.x; i < 128 * WW; i += 256) {
        int c = i >> 6, w = i & 63;
        const float* src = (c < 64) ? feat : deg;
        tile[c][w] = src[(((size_t)b * 64 + (c & 63)) * HH + h) * WW + w];
    }
    __syncthreads();
    float* dst = g_nhwc2 + (((size_t)b * HH + h) * WW) * 128;
    for (int i = threadIdx.x; i < 128 * WW; i += 256) {
        int w = i >> 7, c = i & 127;
        dst[w * 128 + c] = tile[c][w];
    }
}

// ---------------------------------------------------------------------------
// Kernel 2a: deform weight (O,C,3,3) -> g_wtB (m16n8k8 B-frag layout, hi/lo).
// ---------------------------------------------------------------------------
__global__ void transpose_w(const float* __restrict__ w) {
    int i = blockIdx.x * blockDim.x + threadIdx.x;
    if (i >= 9*2*2048) return;
    int k = i / 4096;
    int r = i % 4096;
    int h = r >> 11;
    int e = r & 2047;
    int lane = e & 31;
    int frag = e >> 5;
    int nt = frag & 7, s = frag >> 3;
    int o = nt*8 + (lane >> 2);
    int c0 = s*8 + (lane & 3)*2;
    float v0 = w[(o*CC + c0)*9 + k];
    float v1 = w[(o*CC + c0 + 1)*9 + k];
    float h0 = tf32r(v0), h1 = tf32r(v1);
    g_wtB[i] = h ? make_float2(tf32r(v0 - h0), tf32r(v1 - h1))
                 : make_float2(h0, h1);
}

// ---------------------------------------------------------------------------
// Kernel 2b: om_weight (27,128,3,3) -> g_omB, N padded to 32, hi/lo tf32.
// Index: ((((k*2 + c64)*2 + h)*8 + s)*4 + nt)*32 + lane
// ---------------------------------------------------------------------------
__global__ void transpose_omw(const float* __restrict__ omw) {
    int i = blockIdx.x * blockDim.x + threadIdx.x;
    if (i >= 9*2*2*8*4*32) return;
    int lane = i & 31;
    int r = i >> 5;
    int nt = r & 3;  r >>= 2;
    int s = r & 7;   r >>= 3;
    int h = r & 1;   r >>= 1;
    int c64 = r & 1;
    int k = r >> 1;
    int j = nt*8 + (lane >> 2);
    int c = c64*64 + s*8 + (lane & 3)*2;
    float v0 = 0.f, v1 = 0.f;
    if (j < JJ) {
        v0 = omw[(j*128 + c)*9 + k];
        v1 = omw[(j*128 + c + 1)*9 + k];
    }
    float h0 = tf32r(v0), h1 = tf32r(v1);
    g_omB[i] = h ? make_float2(tf32r(v0 - h0), tf32r(v1 - h1))
                 : make_float2(h0, h1);
}

// ---------------------------------------------------------------------------
// Kernel 3: om conv via mma.tf32: per block 128px x 32j, K = 9 taps x 128 ch.
// A = predicated shifted-window loads (no gather), 2 chunks of 64 ch per tap.
// ---------------------------------------------------------------------------
#define OM_AHI 0
#define OM_ALO 33792
#define OM_B   67584
#define OM_TOT (OM_B + 16384)

__global__ __launch_bounds__(256) void om_gemm(const float* __restrict__ omb) {
    extern __shared__ char sm[];
    int bi = blockIdx.x;
    int b  = bi >> 5;
    int tY = (bi >> 2) & 7;
    int tX = bi & 3;

    int t = threadIdx.x;
    int lane = t & 31;
    int wrp = t >> 5;
    int wm = wrp >> 1, wn = wrp & 1;

    int q = t & 15, px8 = t >> 4;
    int s_smp = q >> 1;
    int lnc = (q & 1) * 2;

    const float4* img = (const float4*)(g_nhwc2 + (size_t)b * HWT * 128);

    float d[2][2][4];
#pragma unroll
    for (int i = 0; i < 2; i++)
#pragma unroll
        for (int j = 0; j < 2; j++)
#pragma unroll
            for (int e = 0; e < 4; e++) d[i][j][e] = 0.f;

    for (int k = 0; k < 9; k++) {
        int ky = k / 3 - 1, kx = k % 3 - 1;
#pragma unroll
        for (int c64 = 0; c64 < 2; c64++) {
            if (k || c64) __syncthreads();

            // B tile (16KB: hi 8KB + lo 8KB)
            {
                const float4* srcB = (const float4*)(g_omB + (size_t)(k*2 + c64) * 2048);
                float4* dstB = (float4*)(sm + OM_B);
#pragma unroll
                for (int i = 0; i < 4; i++) dstB[i * 256 + t] = srcB[i * 256 + t];
            }

            // A tile: shifted window, hi/lo split, fragment-layout STS
#pragma unroll
            for (int j = 0; j < 8; j++) {
                int px = px8 * 8 + j;
                int gy = tY * 8 + (px >> 4), gx = tX * 16 + (px & 15);
                int yy = gy + ky, xx = gx + kx;
                float4 v = make_float4(0.f, 0.f, 0.f, 0.f);
                if (yy >= 0 && yy < HH && xx >= 0 && xx < WW)
                    v = img[(yy * WW + xx) * 32 + c64 * 16 + q];
                float h0 = tf32r(v.x), h1 = tf32r(v.y);
                float h2 = tf32r(v.z), h3 = tf32r(v.w);
                float l0 = tf32r(v.x - h0), l1 = tf32r(v.y - h1);
                float l2 = tf32r(v.z - h2), l3 = tf32r(v.w - h3);

                int mt = px >> 4;
                int r = px & 7;
                int high = (px >> 3) & 1;
                int fo = (mt * 8 + s_smp) * 528 + high * 8;
                int la = (r * 4 + lnc) * 16;
                *(float2*)(sm + OM_AHI + fo + la)      = make_float2(h0, h1);
                *(float2*)(sm + OM_AHI + fo + la + 16) = make_float2(h2, h3);
                *(float2*)(sm + OM_ALO + fo + la)      = make_float2(l0, l1);
                *(float2*)(sm + OM_ALO + fo + la + 16) = make_float2(l2, l3);
            }
            __syncthreads();

            // GEMM: 3 passes (hh, lh, hl)
            const char* Ah = sm + OM_AHI;
            const char* Al = sm + OM_ALO;
            const char* Bh = sm + OM_B;
            const char* Bl = sm + OM_B + 8192;
#pragma unroll
            for (int s = 0; s < 8; s++) {
                int f0 = ((wm * 2 + 0) * 8 + s) * 528 + lane * 16;
                int f1 = ((wm * 2 + 1) * 8 + s) * 528 + lane * 16;
                uint4 ah0 = *(const uint4*)(Ah + f0);
                uint4 ah1 = *(const uint4*)(Ah + f1);
                uint4 al0 = *(const uint4*)(Al + f0);
                uint4 al1 = *(const uint4*)(Al + f1);
#pragma unroll
                for (int nt = 0; nt < 2; nt++) {
                    int fi = ((s * 4 + wn * 2 + nt) * 32 + lane) * 8;
                    uint2 bh = *(const uint2*)(Bh + fi);
                    uint2 bl = *(const uint2*)(Bl + fi);
                    MMA8(d[0][nt], ah0.x, ah0.z, ah0.y, ah0.w, bh.x, bh.y);
                    MMA8(d[0][nt], al0.x, al0.z, al0.y, al0.w, bh.x, bh.y);
                    MMA8(d[0][nt], ah0.x, ah0.z, ah0.y, ah0.w, bl.x, bl.y);
                    MMA8(d[1][nt], ah1.x, ah1.z, ah1.y, ah1.w, bh.x, bh.y);
                    MMA8(d[1][nt], al1.x, al1.z, al1.y, al1.w, bh.x, bh.y);
                    MMA8(d[1][nt], ah1.x, ah1.z, ah1.y, ah1.w, bl.x, bl.y);
                }
            }
        }
    }

    // Epilogue: + bias, write g_om (skip ALL padded j >= 27)
#pragma unroll
    for (int mi = 0; mi < 2; mi++) {
        int pxb = (wm * 2 + mi) * 16 + (lane >> 2);
        int gy0 = tY * 8 + (pxb >> 4), gx0 = tX * 16 + (pxb & 15);
        int px2 = pxb + 8;
        int gy1 = tY * 8 + (px2 >> 4), gx1 = tX * 16 + (px2 & 15);
#pragma unroll
        for (int nt = 0; nt < 2; nt++) {
            int j = wn * 16 + nt * 8 + (lane & 3) * 2;
            size_t base = ((size_t)b * JJ + j) * HWT;
            if (j < JJ) {                               // [R8 bug: unguarded]
                float b0 = omb[j];
                g_om[base + gy0 * WW + gx0] = d[mi][nt][0] + b0;
                g_om[base + gy1 * WW + gx1] = d[mi][nt][2] + b0;
            }
            if (j + 1 < JJ) {
                float b1 = omb[j + 1];
                g_om[base + HWT + gy0 * WW + gx0] = d[mi][nt][1] + b1;
                g_om[base + HWT + gy1 * WW + gx1] = d[mi][nt][3] + b1;
            }
        }
    }
}

// ---------------------------------------------------------------------------
// Kernel 4: deformable conv via mma.tf32 (unchanged).
// ---------------------------------------------------------------------------
#define SM_PQ  0
#define SM_WQ  2048
#define SM_AHI 4096
#define SM_ALO (SM_AHI + 33792)
#define SM_B   (SM_ALO + 33792)
#define SM_TOT (SM_B + 32768)

__global__ __launch_bounds__(256) void deform(float* __restrict__ out) {
    extern __shared__ char sm[];
    int bi = blockIdx.x;
    int b  = bi >> 5;
    int tY = (bi >> 2) & 7;
    int tX = bi & 3;

    int t = threadIdx.x;
    int lane = t & 31;
    int wrp = t >> 5;
    int wm = wrp >> 1, wn = wrp & 1;

    int4*   s_pq = (int4*)(sm + SM_PQ);
    float4* s_wq = (float4*)(sm + SM_WQ);

    const float*  omb_  = g_om + (size_t)b * JJ * HWT;
    const float4* imgf4 = (const float4*)(g_nhwc2 + (size_t)b * HWT * 128);

    int q = t & 15, px8 = t >> 4;
    int s_smp = q >> 1;
    int lnc = (q & 1) * 2;

    float d[2][4][4];
#pragma unroll
    for (int i = 0; i < 2; i++)
#pragma unroll
        for (int j = 0; j < 4; j++)
#pragma unroll
            for (int e = 0; e < 4; e++) d[i][j][e] = 0.f;

    for (int k = 0; k < 9; k++) {
        if (k) __syncthreads();

        if (t < 128) {
            int gy = tY * 8 + (t >> 4), gx = tX * 16 + (t & 15);
            int p = gy * WW + gx;
            float dy = omb_[(2 * k) * HWT + p];
            float dx = omb_[(2 * k + 1) * HWT + p];
            float mv = omb_[(18 + k) * HWT + p];
            float m = 1.f / (1.f + __expf(-mv));
            float y = (float)(gy - 1 + k / 3) + dy;
            float x = (float)(gx - 1 + k % 3) + dx;
            float yf = floorf(y), xf = floorf(x);
            int yi = (int)yf, xi = (int)xf;
            float wy = y - yf, wx = x - xf;
            bool vy0 = (yi >= 0) && (yi < HH);
            bool vy1 = (yi >= -1) && (yi < HH - 1);
            bool vx0 = (xi >= 0) && (xi < WW);
            bool vx1 = (xi >= -1) && (xi < WW - 1);
            float w00 = (vy0 && vx0) ? (1.f - wy) * (1.f - wx) * m : 0.f;
            float w01 = (vy0 && vx1) ? (1.f - wy) * wx * m : 0.f;
            float w10 = (vy1 && vx0) ? wy * (1.f - wx) * m : 0.f;
            float w11 = (vy1 && vx1) ? wy * wx * m : 0.f;
            int y0c = min(max(yi, 0), HH - 1), y1c = min(max(yi + 1, 0), HH - 1);
            int x0c = min(max(xi, 0), WW - 1), x1c = min(max(xi + 1, 0), WW - 1);
            s_pq[t] = make_int4(y0c * WW + x0c, y0c * WW + x1c,
                                y1c * WW + x0c, y1c * WW + x1c);
            s_wq[t] = make_float4(w00, w01, w10, w11);
        }
        {
            const float4* srcB = (const float4*)(g_wtB + (size_t)k * 4096);
            float4* dstB = (float4*)(sm + SM_B);
#pragma unroll
            for (int i = 0; i < 8; i++) dstB[i * 256 + t] = srcB[i * 256 + t];
        }
        __syncthreads();

#pragma unroll
        for (int j = 0; j < 8; j++) {
            int px = px8 * 8 + j;
            int4 pq = s_pq[px];
            float4 wq = s_wq[px];
            float a0 = 0.f, a1 = 0.f, a2 = 0.f, a3 = 0.f;
            float4 v;
            v = imgf4[pq.x * 32 + q];
            a0 = fmaf(wq.x, v.x, a0); a1 = fmaf(wq.x, v.y, a1);
            a2 = fmaf(wq.x, v.z, a2); a3 = fmaf(wq.x, v.w, a3);
            v = imgf4[pq.y * 32 + q];
            a0 = fmaf(wq.y, v.x, a0); a1 = fmaf(wq.y, v.y, a1);
            a2 = fmaf(wq.y, v.z, a2); a3 = fmaf(wq.y, v.w, a3);
            v = imgf4[pq.z * 32 + q];
            a0 = fmaf(wq.z, v.x, a0); a1 = fmaf(wq.z, v.y, a1);
            a2 = fmaf(wq.z, v.z, a2); a3 = fmaf(wq.z, v.w, a3);
            v = imgf4[pq.w * 32 + q];
            a0 = fmaf(wq.w, v.x, a0); a1 = fmaf(wq.w, v.y, a1);
            a2 = fmaf(wq.w, v.z, a2); a3 = fmaf(wq.w, v.w, a3);

            float h0 = tf32r(a0), h1 = tf32r(a1), h2 = tf32r(a2), h3 = tf32r(a3);
            float l0 = tf32r(a0 - h0), l1 = tf32r(a1 - h1);
            float l2 = tf32r(a2 - h2), l3 = tf32r(a3 - h3);

            int mt = px >> 4;
            int r = px & 7;
            int high = (px >> 3) & 1;
            int fo = (mt * 8 + s_smp) * 528 + high * 8;
            int la = (r * 4 + lnc) * 16;
            *(float2*)(sm + SM_AHI + fo + la)      = make_float2(h0, h1);
            *(float2*)(sm + SM_AHI + fo + la + 16) = make_float2(h2, h3);
            *(float2*)(sm + SM_ALO + fo + la)      = make_float2(l0, l1);
            *(float2*)(sm + SM_ALO + fo + la + 16) = make_float2(l2, l3);
        }
        __syncthreads();

        {
            const char* Ah = sm + SM_AHI;
            const char* Al = sm + SM_ALO;
            const char* Bh = sm + SM_B;
            const char* Bl = sm + SM_B + 16384;
#pragma unroll
            for (int s = 0; s < 8; s++) {
                int f0 = ((wm * 2 + 0) * 8 + s) * 528 + lane * 16;
                int f1 = ((wm * 2 + 1) * 8 + s) * 528 + lane * 16;
                uint4 ah0 = *(const uint4*)(Ah + f0);
                uint4 ah1 = *(const uint4*)(Ah + f1);
                uint4 al0 = *(const uint4*)(Al + f0);
                uint4 al1 = *(const uint4*)(Al + f1);
#pragma unroll
                for (int nt = 0; nt < 4; nt++) {
                    int fi = ((s * 8 + wn * 4 + nt) * 32 + lane) * 8;
                    uint2 bh = *(const uint2*)(Bh + fi);
                    uint2 bl = *(const uint2*)(Bl + fi);
                    MMA8(d[0][nt], ah0.x, ah0.z, ah0.y, ah0.w, bh.x, bh.y);
                    MMA8(d[0][nt], al0.x, al0.z, al0.y, al0.w, bh.x, bh.y);
                    MMA8(d[0][nt], ah0.x, ah0.z, ah0.y, ah0.w, bl.x, bl.y);
                    MMA8(d[1][nt], ah1.x, ah1.z, ah1.y, ah1.w, bh.x, bh.y);
                    MMA8(d[1][nt], al1.x, al1.z, al1.y, al1.w, bh.x, bh.y);
                    MMA8(d[1][nt], ah1.x, ah1.z, ah1.y, ah1.w, bl.x, bl.y);
                }
            }
        }
    }

#pragma unroll
    for (int mi = 0; mi < 2; mi++) {
        int pxb = (wm * 2 + mi) * 16 + (lane >> 2);
        int gy0 = tY * 8 + (pxb >> 4), gx0 = tX * 16 + (pxb & 15);
        int px2 = pxb + 8;
        int gy1 = tY * 8 + (px2 >> 4), gx1 = tX * 16 + (px2 & 15);
#pragma unroll
        for (int nt = 0; nt < 4; nt++) {
            int o = wn * 32 + nt * 8 + (lane & 3) * 2;
            size_t base = ((size_t)b * OO + o) * HWT;
            out[base + gy0 * WW + gx0]       = d[mi][nt][0];
            out[base + HWT + gy0 * WW + gx0] = d[mi][nt][1];
            out[base + gy1 * WW + gx1]       = d[mi][nt][2];
            out[base + HWT + gy1 * WW + gx1] = d[mi][nt][3];
        }
    }
}

// ---------------------------------------------------------------------------
extern "C" void kernel_launch(void* const* d_in, const int* in_sizes, int n_in,
                              void* d_out, int out_size) {
    const float* input_feat = (const float*)d_in[0];
    const float* degrad     = (const float*)d_in[1];
    const float* weight     = (const float*)d_in[2];
    const float* om_weight  = (const float*)d_in[3];
    const float* om_bias    = (const float*)d_in[4];
    float* out = (float*)d_out;

    cudaFuncSetAttribute(om_gemm, cudaFuncAttributeMaxDynamicSharedMemorySize, OM_TOT);
    cudaFuncSetAttribute(deform, cudaFuncAttributeMaxDynamicSharedMemorySize, SM_TOT);

    transpose_nhwc2<<<BB * HH, 256>>>(input_feat, degrad);
    transpose_w<<<(9 * 2 * 2048 + 255) / 256, 256>>>(weight);
    transpose_omw<<<(9*2*2*8*4*32 + 255) / 256, 256>>>(om_weight);
    om_gemm<<<BB * 32, 256, OM_TOT>>>(om_bias);
    deform<<<BB * 32, 256, SM_TOT>>>(out);
}

// round 10
// speedup vs baseline: 2.5030x; 1.2464x over previous
#include <cuda_runtime.h>
#include <cstdint>

#define BB 8
#define CC 64
#define HH 64
#define WW 64
#define OO 64
#define HWT (HH*WW)
#define JJ 27

// tf32 round (keeps top 10 mantissa bits)
__device__ __forceinline__ float tf32r(float x) {
    unsigned u;
    asm("cvt.rna.tf32.f32 %0, %1;" : "=r"(u) : "f"(x));
    return __uint_as_float(u);
}

// mma.sync m16n8k8 tf32: D += A*B (fp32 accum)
#define MMA8(D, A0, A1, A2, A3, B0, B1)                                   \
    asm volatile("mma.sync.aligned.m16n8k8.row.col.f32.tf32.tf32.f32 "     \
        "{%0,%1,%2,%3}, {%4,%5,%6,%7}, {%8,%9}, {%0,%1,%2,%3};"            \
        : "+f"((D)[0]), "+f"((D)[1]), "+f"((D)[2]), "+f"((D)[3])           \
        : "r"(A0), "r"(A1), "r"(A2), "r"(A3), "r"(B0), "r"(B1))

// Scratch (device globals: no allocation allowed)
__device__ float  g_nhwc2[BB*HH*WW*128];   // concat(feat, degrad) NHWC, 128 ch
__device__ float  g_om[BB*JJ*HWT];         // offset/mask conv output
__device__ __align__(16) float2 g_wtB[9*2*2048];     // deform weights hi/lo B-frags
__device__ __align__(16) float2 g_omB[9*2*8*4*32];   // om weights hi-only B-frags

// ---------------------------------------------------------------------------
// Kernel 1: NCHW feat+degrad -> g_nhwc2[b][y][x][128]. One block per (b,h).
// ---------------------------------------------------------------------------
__global__ __launch_bounds__(256) void transpose_nhwc2(const float* __restrict__ feat,
                                                       const float* __restrict__ deg) {
    int bh = blockIdx.x;
    int b = bh / HH, h = bh % HH;
    __shared__ float tile[128][WW + 1];
    for (int i = threadIdx.x; i < 128 * WW; i += 256) {
        int c = i >> 6, w = i & 63;
        const float* src = (c < 64) ? feat : deg;
        tile[c][w] = src[(((size_t)b * 64 + (c & 63)) * HH + h) * WW + w];
    }
    __syncthreads();
    float* dst = g_nhwc2 + (((size_t)b * HH + h) * WW) * 128;
    for (int i = threadIdx.x; i < 128 * WW; i += 256) {
        int w = i >> 7, c = i & 127;
        dst[w * 128 + c] = tile[c][w];
    }
}

// ---------------------------------------------------------------------------
// Kernel 2a: deform weight (O,C,3,3) -> g_wtB (m16n8k8 B-frag layout, hi/lo).
// ---------------------------------------------------------------------------
__global__ void transpose_w(const float* __restrict__ w) {
    int i = blockIdx.x * blockDim.x + threadIdx.x;
    if (i >= 9*2*2048) return;
    int k = i / 4096;
    int r = i % 4096;
    int h = r >> 11;
    int e = r & 2047;
    int lane = e & 31;
    int frag = e >> 5;
    int nt = frag & 7, s = frag >> 3;
    int o = nt*8 + (lane >> 2);
    int c0 = s*8 + (lane & 3)*2;
    float v0 = w[(o*CC + c0)*9 + k];
    float v1 = w[(o*CC + c0 + 1)*9 + k];
    float h0 = tf32r(v0), h1 = tf32r(v1);
    g_wtB[i] = h ? make_float2(tf32r(v0 - h0), tf32r(v1 - h1))
                 : make_float2(h0, h1);
}

// ---------------------------------------------------------------------------
// Kernel 2b: om_weight (27,128,3,3) -> g_omB, N padded to 32, hi-only tf32.
// Index: (((k*2 + c64)*8 + s)*4 + nt)*32 + lane
// ---------------------------------------------------------------------------
__global__ void transpose_omw(const float* __restrict__ omw) {
    int i = blockIdx.x * blockDim.x + threadIdx.x;
    if (i >= 9*2*8*4*32) return;
    int lane = i & 31;
    int r = i >> 5;
    int nt = r & 3;  r >>= 2;
    int s = r & 7;   r >>= 3;
    int c64 = r & 1;
    int k = r >> 1;
    int j = nt*8 + (lane >> 2);
    int c = c64*64 + s*8 + (lane & 3)*2;
    float v0 = 0.f, v1 = 0.f;
    if (j < JJ) {
        v0 = omw[(j*128 + c)*9 + k];
        v1 = omw[(j*128 + c + 1)*9 + k];
    }
    g_omB[i] = make_float2(tf32r(v0), tf32r(v1));
}

// ---------------------------------------------------------------------------
// Kernel 3: om conv via mma.tf32, SINGLE PASS (offsets tolerate tf32 error).
// Per block 128px x 32j, K = 9 taps x 128 ch. smem 41KB -> 2+ blocks/SM.
// ---------------------------------------------------------------------------
#define OM_AHI 0
#define OM_B   33792
#define OM_TOT (OM_B + 8192)

__global__ __launch_bounds__(256) void om_gemm(const float* __restrict__ omb) {
    extern __shared__ char sm[];
    int bi = blockIdx.x;
    int b  = bi >> 5;
    int tY = (bi >> 2) & 7;
    int tX = bi & 3;

    int t = threadIdx.x;
    int lane = t & 31;
    int wrp = t >> 5;
    int wm = wrp >> 1, wn = wrp & 1;

    int q = t & 15, px8 = t >> 4;
    int s_smp = q >> 1;
    int lnc = (q & 1) * 2;

    const float4* img = (const float4*)(g_nhwc2 + (size_t)b * HWT * 128);

    float d[2][2][4];
#pragma unroll
    for (int i = 0; i < 2; i++)
#pragma unroll
        for (int j = 0; j < 2; j++)
#pragma unroll
            for (int e = 0; e < 4; e++) d[i][j][e] = 0.f;

    for (int k = 0; k < 9; k++) {
        int ky = k / 3 - 1, kx = k % 3 - 1;
#pragma unroll
        for (int c64 = 0; c64 < 2; c64++) {
            if (k || c64) __syncthreads();

            // B tile (8KB, hi only)
            {
                const float4* srcB = (const float4*)(g_omB + (size_t)(k*2 + c64) * 1024);
                float4* dstB = (float4*)(sm + OM_B);
#pragma unroll
                for (int i = 0; i < 2; i++) dstB[i * 256 + t] = srcB[i * 256 + t];
            }

            // A tile: shifted window, hi only, fragment-layout STS
#pragma unroll
            for (int j = 0; j < 8; j++) {
                int px = px8 * 8 + j;
                int gy = tY * 8 + (px >> 4), gx = tX * 16 + (px & 15);
                int yy = gy + ky, xx = gx + kx;
                float4 v = make_float4(0.f, 0.f, 0.f, 0.f);
                if (yy >= 0 && yy < HH && xx >= 0 && xx < WW)
                    v = img[(yy * WW + xx) * 32 + c64 * 16 + q];
                float h0 = tf32r(v.x), h1 = tf32r(v.y);
                float h2 = tf32r(v.z), h3 = tf32r(v.w);

                int mt = px >> 4;
                int r = px & 7;
                int high = (px >> 3) & 1;
                int fo = (mt * 8 + s_smp) * 528 + high * 8;
                int la = (r * 4 + lnc) * 16;
                *(float2*)(sm + OM_AHI + fo + la)      = make_float2(h0, h1);
                *(float2*)(sm + OM_AHI + fo + la + 16) = make_float2(h2, h3);
            }
            __syncthreads();

            // GEMM: single pass
            const char* Ah = sm + OM_AHI;
            const char* Bh = sm + OM_B;
#pragma unroll
            for (int s = 0; s < 8; s++) {
                int f0 = ((wm * 2 + 0) * 8 + s) * 528 + lane * 16;
                int f1 = ((wm * 2 + 1) * 8 + s) * 528 + lane * 16;
                uint4 ah0 = *(const uint4*)(Ah + f0);
                uint4 ah1 = *(const uint4*)(Ah + f1);
#pragma unroll
                for (int nt = 0; nt < 2; nt++) {
                    int fi = ((s * 4 + wn * 2 + nt) * 32 + lane) * 8;
                    uint2 bh = *(const uint2*)(Bh + fi);
                    MMA8(d[0][nt], ah0.x, ah0.z, ah0.y, ah0.w, bh.x, bh.y);
                    MMA8(d[1][nt], ah1.x, ah1.z, ah1.y, ah1.w, bh.x, bh.y);
                }
            }
        }
    }

    // Epilogue: + bias, write g_om (skip ALL padded j >= 27)
#pragma unroll
    for (int mi = 0; mi < 2; mi++) {
        int pxb = (wm * 2 + mi) * 16 + (lane >> 2);
        int gy0 = tY * 8 + (pxb >> 4), gx0 = tX * 16 + (pxb & 15);
        int px2 = pxb + 8;
        int gy1 = tY * 8 + (px2 >> 4), gx1 = tX * 16 + (px2 & 15);
#pragma unroll
        for (int nt = 0; nt < 2; nt++) {
            int j = wn * 16 + nt * 8 + (lane & 3) * 2;
            size_t base = ((size_t)b * JJ + j) * HWT;
            if (j < JJ) {
                float b0 = omb[j];
                g_om[base + gy0 * WW + gx0] = d[mi][nt][0] + b0;
                g_om[base + gy1 * WW + gx1] = d[mi][nt][2] + b0;
            }
            if (j + 1 < JJ) {
                float b1 = omb[j + 1];
                g_om[base + HWT + gy0 * WW + gx0] = d[mi][nt][1] + b1;
                g_om[base + HWT + gy1 * WW + gx1] = d[mi][nt][3] + b1;
            }
        }
    }
}

// ---------------------------------------------------------------------------
// Kernel 4: deformable conv via mma.tf32, 3-pass hi/lo (value path: unchanged).
// ---------------------------------------------------------------------------
#define SM_PQ  0
#define SM_WQ  2048
#define SM_AHI 4096
#define SM_ALO (SM_AHI + 33792)
#define SM_B   (SM_ALO + 33792)
#define SM_TOT (SM_B + 32768)

__global__ __launch_bounds__(256) void deform(float* __restrict__ out) {
    extern __shared__ char sm[];
    int bi = blockIdx.x;
    int b  = bi >> 5;
    int tY = (bi >> 2) & 7;
    int tX = bi & 3;

    int t = threadIdx.x;
    int lane = t & 31;
    int wrp = t >> 5;
    int wm = wrp >> 1, wn = wrp & 1;

    int4*   s_pq = (int4*)(sm + SM_PQ);
    float4* s_wq = (float4*)(sm + SM_WQ);

    const float*  omb_  = g_om + (size_t)b * JJ * HWT;
    const float4* imgf4 = (const float4*)(g_nhwc2 + (size_t)b * HWT * 128);

    int q = t & 15, px8 = t >> 4;
    int s_smp = q >> 1;
    int lnc = (q & 1) * 2;

    float d[2][4][4];
#pragma unroll
    for (int i = 0; i < 2; i++)
#pragma unroll
        for (int j = 0; j < 4; j++)
#pragma unroll
            for (int e = 0; e < 4; e++) d[i][j][e] = 0.f;

    for (int k = 0; k < 9; k++) {
        if (k) __syncthreads();

        if (t < 128) {
            int gy = tY * 8 + (t >> 4), gx = tX * 16 + (t & 15);
            int p = gy * WW + gx;
            float dy = omb_[(2 * k) * HWT + p];
            float dx = omb_[(2 * k + 1) * HWT + p];
            float mv = omb_[(18 + k) * HWT + p];
            float m = 1.f / (1.f + __expf(-mv));
            float y = (float)(gy - 1 + k / 3) + dy;
            float x = (float)(gx - 1 + k % 3) + dx;
            float yf = floorf(y), xf = floorf(x);
            int yi = (int)yf, xi = (int)xf;
            float wy = y - yf, wx = x - xf;
            bool vy0 = (yi >= 0) && (yi < HH);
            bool vy1 = (yi >= -1) && (yi < HH - 1);
            bool vx0 = (xi >= 0) && (xi < WW);
            bool vx1 = (xi >= -1) && (xi < WW - 1);
            float w00 = (vy0 && vx0) ? (1.f - wy) * (1.f - wx) * m : 0.f;
            float w01 = (vy0 && vx1) ? (1.f - wy) * wx * m : 0.f;
            float w10 = (vy1 && vx0) ? wy * (1.f - wx) * m : 0.f;
            float w11 = (vy1 && vx1) ? wy * wx * m : 0.f;
            int y0c = min(max(yi, 0), HH - 1), y1c = min(max(yi + 1, 0), HH - 1);
            int x0c = min(max(xi, 0), WW - 1), x1c = min(max(xi + 1, 0), WW - 1);
            s_pq[t] = make_int4(y0c * WW + x0c, y0c * WW + x1c,
                                y1c * WW + x0c, y1c * WW + x1c);
            s_wq[t] = make_float4(w00, w01, w10, w11);
        }
        {
            const float4* srcB = (const float4*)(g_wtB + (size_t)k * 4096);
            float4* dstB = (float4*)(sm + SM_B);
#pragma unroll
            for (int i = 0; i < 8; i++) dstB[i * 256 + t] = srcB[i * 256 + t];
        }
        __syncthreads();

#pragma unroll
        for (int j = 0; j < 8; j++) {
            int px = px8 * 8 + j;
            int4 pq = s_pq[px];
            float4 wq = s_wq[px];
            float a0 = 0.f, a1 = 0.f, a2 = 0.f, a3 = 0.f;
            float4 v;
            v = imgf4[pq.x * 32 + q];
            a0 = fmaf(wq.x, v.x, a0); a1 = fmaf(wq.x, v.y, a1);
            a2 = fmaf(wq.x, v.z, a2); a3 = fmaf(wq.x, v.w, a3);
            v = imgf4[pq.y * 32 + q];
            a0 = fmaf(wq.y, v.x, a0); a1 = fmaf(wq.y, v.y, a1);
            a2 = fmaf(wq.y, v.z, a2); a3 = fmaf(wq.y, v.w, a3);
            v = imgf4[pq.z * 32 + q];
            a0 = fmaf(wq.z, v.x, a0); a1 = fmaf(wq.z, v.y, a1);
            a2 = fmaf(wq.z, v.z, a2); a3 = fmaf(wq.z, v.w, a3);
            v = imgf4[pq.w * 32 + q];
            a0 = fmaf(wq.w, v.x, a0); a1 = fmaf(wq.w, v.y, a1);
            a2 = fmaf(wq.w, v.z, a2); a3 = fmaf(wq.w, v.w, a3);

            float h0 = tf32r(a0), h1 = tf32r(a1), h2 = tf32r(a2), h3 = tf32r(a3);
            float l0 = tf32r(a0 - h0), l1 = tf32r(a1 - h1);
            float l2 = tf32r(a2 - h2), l3 = tf32r(a3 - h3);

            int mt = px >> 4;
            int r = px & 7;
            int high = (px >> 3) & 1;
            int fo = (mt * 8 + s_smp) * 528 + high * 8;
            int la = (r * 4 + lnc) * 16;
            *(float2*)(sm + SM_AHI + fo + la)      = make_float2(h0, h1);
            *(float2*)(sm + SM_AHI + fo + la + 16) = make_float2(h2, h3);
            *(float2*)(sm + SM_ALO + fo + la)      = make_float2(l0, l1);
            *(float2*)(sm + SM_ALO + fo + la + 16) = make_float2(l2, l3);
        }
        __syncthreads();

        {
            const char* Ah = sm + SM_AHI;
            const char* Al = sm + SM_ALO;
            const char* Bh = sm + SM_B;
            const char* Bl = sm + SM_B + 16384;
#pragma unroll
            for (int s = 0; s < 8; s++) {
                int f0 = ((wm * 2 + 0) * 8 + s) * 528 + lane * 16;
                int f1 = ((wm * 2 + 1) * 8 + s) * 528 + lane * 16;
                uint4 ah0 = *(const uint4*)(Ah + f0);
                uint4 ah1 = *(const uint4*)(Ah + f1);
                uint4 al0 = *(const uint4*)(Al + f0);
                uint4 al1 = *(const uint4*)(Al + f1);
#pragma unroll
                for (int nt = 0; nt < 4; nt++) {
                    int fi = ((s * 8 + wn * 4 + nt) * 32 + lane) * 8;
                    uint2 bh = *(const uint2*)(Bh + fi);
                    uint2 bl = *(const uint2*)(Bl + fi);
                    MMA8(d[0][nt], ah0.x, ah0.z, ah0.y, ah0.w, bh.x, bh.y);
                    MMA8(d[0][nt], al0.x, al0.z, al0.y, al0.w, bh.x, bh.y);
                    MMA8(d[0][nt], ah0.x, ah0.z, ah0.y, ah0.w, bl.x, bl.y);
                    MMA8(d[1][nt], ah1.x, ah1.z, ah1.y, ah1.w, bh.x, bh.y);
                    MMA8(d[1][nt], al1.x, al1.z, al1.y, al1.w, bh.x, bh.y);
                    MMA8(d[1][nt], ah1.x, ah1.z, ah1.y, ah1.w, bl.x, bl.y);
                }
            }
        }
    }

#pragma unroll
    for (int mi = 0; mi < 2; mi++) {
        int pxb = (wm * 2 + mi) * 16 + (lane >> 2);
        int gy0 = tY * 8 + (pxb >> 4), gx0 = tX * 16 + (pxb & 15);
        int px2 = pxb + 8;
        int gy1 = tY * 8 + (px2 >> 4), gx1 = tX * 16 + (px2 & 15);
#pragma unroll
        for (int nt = 0; nt < 4; nt++) {
            int o = wn * 32 + nt * 8 + (lane & 3) * 2;
            size_t base = ((size_t)b * OO + o) * HWT;
            out[base + gy0 * WW + gx0]       = d[mi][nt][0];
            out[base + HWT + gy0 * WW + gx0] = d[mi][nt][1];
            out[base + gy1 * WW + gx1]       = d[mi][nt][2];
            out[base + HWT + gy1 * WW + gx1] = d[mi][nt][3];
        }
    }
}

// ---------------------------------------------------------------------------
extern "C" void kernel_launch(void* const* d_in, const int* in_sizes, int n_in,
                              void* d_out, int out_size) {
    const float* input_feat = (const float*)d_in[0];
    const float* degrad     = (const float*)d_in[1];
    const float* weight     = (const float*)d_in[2];
    const float* om_weight  = (const float*)d_in[3];
    const float* om_bias    = (const float*)d_in[4];
    float* out = (float*)d_out;

    cudaFuncSetAttribute(om_gemm, cudaFuncAttributeMaxDynamicSharedMemorySize, OM_TOT);
    cudaFuncSetAttribute(deform, cudaFuncAttributeMaxDynamicSharedMemorySize, SM_TOT);

    transpose_nhwc2<<<BB * HH, 256>>>(input_feat, degrad);
    transpose_w<<<(9 * 2 * 2048 + 255) / 256, 256>>>(weight);
    transpose_omw<<<(9*2*8*4*32 + 255) / 256, 256>>>(om_weight);
    om_gemm<<<BB * 32, 256, OM_TOT>>>(om_bias);
    deform<<<BB * 32, 256, SM_TOT>>>(out);
}